// round 7
// baseline (speedup 1.0000x reference)
#include <cuda_runtime.h>
#include <math.h>
#include <stdint.h>

// Problem constants
#define Bc   4
#define Sc   1024
#define Dc   1024
#define Hc   16
#define DHc  64
#define Fc   4096
#define TOK  4096          // B*S
#define SIXD 6144          // 6*D
#define TOKD ((size_t)TOK * Dc)   // 4M
#define TOKF ((size_t)TOK * Fc)   // 16M

// k-permutation within each 8-block: position of original k is
// ((k&3)<<1)|(k>>2)  -> order 0,4,1,5,2,6,3,7. Applies to ALL GEMM inputs.
#define KPERM8(k) (((k) & ~7) | (((k) & 3) << 1) | (((k) >> 2) & 1))

// ---------------- scratch (no allocations allowed) ----------------
__device__ float g_st[Bc * Dc];
__device__ float g_ada[Bc * SIXD];
__device__ float g_nx[TOK * Dc];
__device__ float g_w[(size_t)29 << 20];     // transposed+rounded+permuted weights [N][Kp]
__device__ float g_qkv[12 * TOK * Dc];
__device__ float g_ao4[4 * TOK * Dc];       // attention outputs (k-permuted layout)
__device__ float g_obr[4 * TOK * Dc];
__device__ float g_gate[TOK * 4];
__device__ float g_fused[TOK * Dc];         // k-permuted
__device__ float g_xmid[TOK * Dc];
__device__ float g_h[2 * TOK * Fc];         // h1, h3 (h1 becomes permuted after swiglu)

// weight scratch offsets (floats)
#define WQKV 0
#define WO   ((size_t)12 << 20)
#define WFUS ((size_t)16 << 20)
#define W1   ((size_t)17 << 20)
#define W3   ((size_t)21 << 20)
#define W2   ((size_t)25 << 20)

// ---------------- ptx helpers ----------------
__device__ __forceinline__ float to_tf32(float x) {
    float r;
    asm("cvt.rna.tf32.f32 %0, %1;" : "=f"(r) : "f"(x));
    return r;
}
__device__ __forceinline__ void mma_tf32(float* c, uint32_t a0, uint32_t a1,
                                         uint32_t a2, uint32_t a3,
                                         uint32_t b0, uint32_t b1) {
    asm("mma.sync.aligned.m16n8k8.row.col.f32.tf32.tf32.f32 "
        "{%0,%1,%2,%3},{%4,%5,%6,%7},{%8,%9},{%0,%1,%2,%3};"
        : "+f"(c[0]), "+f"(c[1]), "+f"(c[2]), "+f"(c[3])
        : "r"(a0), "r"(a1), "r"(a2), "r"(a3), "r"(b0), "r"(b1));
}
__device__ __forceinline__ void cp16(void* smem, const void* g) {
    uint32_t s = (uint32_t)__cvta_generic_to_shared(smem);
    asm volatile("cp.async.cg.shared.global [%0], [%1], 16;" :: "r"(s), "l"(g));
}
__device__ __forceinline__ void cp_commit() {
    asm volatile("cp.async.commit_group;");
}
template <int N>
__device__ __forceinline__ void cp_wait() {
    asm volatile("cp.async.wait_group %0;" :: "n"(N));
}

// ---------------- weight transpose + tf32 round + k-permute ----------------
// in: W[Kd][Nd] row-major -> out: Wt[Nd][Kd-permuted]
__global__ __launch_bounds__(256) void wtrans_k(const float* __restrict__ in,
                                                float* __restrict__ out,
                                                int Kd, int Nd) {
    __shared__ float tile[32][33];
    int n0 = blockIdx.x * 32, k0 = blockIdx.y * 32;
    int tx = threadIdx.x & 31, ty = threadIdx.x >> 5;   // 32 x 8
    #pragma unroll
    for (int i = 0; i < 32; i += 8)
        tile[ty + i][tx] = in[(size_t)(k0 + ty + i) * Nd + n0 + tx];
    __syncthreads();
    int kp = k0 + KPERM8(tx);
    #pragma unroll
    for (int i = 0; i < 32; i += 8)
        out[(size_t)(n0 + ty + i) * Kd + kp] = to_tf32(tile[tx][ty + i]);
}

struct TP17 { const float* p[17]; };
__global__ __launch_bounds__(256) void wtrans17_k(TP17 tp, float* __restrict__ out) {
    __shared__ float tile[32][33];
    const float* in = tp.p[blockIdx.z];
    float* o = out + ((size_t)blockIdx.z << 20);
    int n0 = blockIdx.x * 32, k0 = blockIdx.y * 32;
    int tx = threadIdx.x & 31, ty = threadIdx.x >> 5;
    #pragma unroll
    for (int i = 0; i < 32; i += 8)
        tile[ty + i][tx] = in[(size_t)(k0 + ty + i) * Dc + n0 + tx];
    __syncthreads();
    int kp = k0 + KPERM8(tx);
    #pragma unroll
    for (int i = 0; i < 32; i += 8)
        o[(size_t)(n0 + ty + i) * Dc + kp] = to_tf32(tile[tx][ty + i]);
}

// ---------------- elementwise helpers ----------------
__global__ void silu_k(const float* __restrict__ in, float* __restrict__ out, int n) {
    int i = blockIdx.x * blockDim.x + threadIdx.x;
    if (i < n) { float v = in[i]; out[i] = v / (1.f + __expf(-v)); }
}

__global__ __launch_bounds__(256) void ada_k(const float* __restrict__ st,
                                             const float* __restrict__ W,
                                             const float* __restrict__ bias,
                                             float* __restrict__ out) {
    int o = blockIdx.x * 8 + (threadIdx.x >> 5);
    int lane = threadIdx.x & 31;
    int b = o / SIXD, n = o - b * SIXD;
    float acc = 0.f;
    for (int k = lane; k < Dc; k += 32)
        acc = fmaf(st[b * Dc + k], W[(size_t)k * SIXD + n], acc);
    #pragma unroll
    for (int off = 16; off; off >>= 1) acc += __shfl_xor_sync(~0u, acc, off);
    if (!lane) out[o] = acc + bias[n];
}

// nx = tf32( (LN(x)*g+b)*(1+sc)+sh ), written in k-permuted layout
__global__ __launch_bounds__(256) void ln_mod_k(const float* __restrict__ X,
                                                const float* __restrict__ gam,
                                                const float* __restrict__ bet,
                                                const float* __restrict__ ada,
                                                int sh_off, int sc_off,
                                                float* __restrict__ out) {
    int t = blockIdx.x;
    int b = t >> 10;
    int tid = threadIdx.x;
    const float* xr = X + (size_t)t * Dc;
    float s = 0.f, ss = 0.f;
    for (int i = tid; i < Dc; i += 256) { float v = xr[i]; s += v; ss = fmaf(v, v, ss); }
    __shared__ float r1[8], r2[8];
    __shared__ float muS, rsS;
    #pragma unroll
    for (int off = 16; off; off >>= 1) {
        s  += __shfl_xor_sync(~0u, s,  off);
        ss += __shfl_xor_sync(~0u, ss, off);
    }
    if ((tid & 31) == 0) { r1[tid >> 5] = s; r2[tid >> 5] = ss; }
    __syncthreads();
    if (tid < 32) {
        float a = (tid < 8) ? r1[tid] : 0.f;
        float c = (tid < 8) ? r2[tid] : 0.f;
        #pragma unroll
        for (int off = 4; off; off >>= 1) {
            a += __shfl_xor_sync(~0u, a, off);
            c += __shfl_xor_sync(~0u, c, off);
        }
        if (tid == 0) {
            float mu = a * (1.f / Dc);
            float var = c * (1.f / Dc) - mu * mu;
            muS = mu; rsS = rsqrtf(var + 1e-6f);
        }
    }
    __syncthreads();
    float mu = muS, rs = rsS;
    const float* ar = ada + b * SIXD;
    float* orow = out + (size_t)t * Dc;
    for (int i = tid; i < Dc; i += 256) {
        float v = (xr[i] - mu) * rs * gam[i] + bet[i];
        orow[KPERM8(i)] = to_tf32(fmaf(v, 1.f + ar[sc_off + i], ar[sh_off + i]));
    }
}

// ---------------- TF32 TC GEMM, fragment-paired layout ----------------
// C = A[M,Kp] @ Bt[N,Kp]^T; 128x128 CTA tile, 8 warps 64x32; 3-stage cp.async.
// Inputs A and Bt are k-permuted so every fragment pair is one LDS.64.
// resid != nullptr: C[t,n] = resid[t,n] + gate[(t>>10)*SIXD + n] * acc
#define AP   20
#define ASZf (128 * AP)            // 2560 floats per matrix per stage
#define STGf (2 * ASZf)            // 5120 floats per stage
#define NSTG 3
#define GEMM_SMEM (NSTG * STGf * 4)   // 61440 B

__global__ __launch_bounds__(256, 2) void gemm_tc(
    const float* __restrict__ A, size_t azs,
    const float* __restrict__ Bt, size_t bzs,
    float* __restrict__ C, size_t czs,
    int M, int N, int K,
    const float* __restrict__ resid, const float* __restrict__ gate) {
    extern __shared__ float sm[];
    #define ASI(st, m, k) sm[(st) * STGf + (m) * AP + (k)]
    #define BSI(st, n, k) sm[(st) * STGf + ASZf + (n) * AP + (k)]

    A += azs * blockIdx.z; Bt += bzs * blockIdx.z; C += czs * blockIdx.z;

    int tid = threadIdx.x;
    int bx = blockIdx.x, by = blockIdx.y;
    int w = tid >> 5, lane = tid & 31;
    int wm = (w >> 2) * 64, wn = (w & 3) * 32;
    int g = lane >> 2, t = lane & 3;

    float acc[4][4][4];
    #pragma unroll
    for (int i = 0; i < 4; i++)
        #pragma unroll
        for (int j = 0; j < 4; j++)
            #pragma unroll
            for (int r = 0; r < 4; r++) acc[i][j][r] = 0.f;

    const float* Ag = A + (size_t)(by * 128) * K;
    const float* Bg = Bt + (size_t)(bx * 128) * K;

    int row0 = tid >> 2, c0 = (tid & 3) << 2;   // 64 rows x 4 granules
    int row1 = row0 + 64;

    auto load_stage = [&](int st, int k0) {
        cp16(&ASI(st, row0, c0), Ag + (size_t)row0 * K + k0 + c0);
        cp16(&ASI(st, row1, c0), Ag + (size_t)row1 * K + k0 + c0);
        cp16(&BSI(st, row0, c0), Bg + (size_t)row0 * K + k0 + c0);
        cp16(&BSI(st, row1, c0), Bg + (size_t)row1 * K + k0 + c0);
    };

    load_stage(0, 0);  cp_commit();
    load_stage(1, 16); cp_commit();
    int cur = 0;

    for (int k0 = 0; k0 < K; k0 += 16) {
        cp_wait<1>();
        __syncthreads();
        if (k0 + 32 < K) {
            int nst = cur + 2; if (nst >= NSTG) nst -= NSTG;
            load_stage(nst, k0 + 32);
        }
        cp_commit();

        #pragma unroll
        for (int ks = 0; ks < 16; ks += 8) {
            int kp = ks + 2 * t;           // paired (kLo,kHi) at perm positions
            uint32_t af[4][4], bf[4][2];
            #pragma unroll
            for (int i = 0; i < 4; i++) {
                int m0 = wm + 16 * i + g;
                float2 lo = *(const float2*)&ASI(cur, m0, kp);
                float2 hi = *(const float2*)&ASI(cur, m0 + 8, kp);
                af[i][0] = __float_as_uint(lo.x);
                af[i][1] = __float_as_uint(hi.x);
                af[i][2] = __float_as_uint(lo.y);
                af[i][3] = __float_as_uint(hi.y);
            }
            #pragma unroll
            for (int j = 0; j < 4; j++) {
                int n0 = wn + 8 * j + g;
                float2 bv = *(const float2*)&BSI(cur, n0, kp);
                bf[j][0] = __float_as_uint(bv.x);
                bf[j][1] = __float_as_uint(bv.y);
            }
            #pragma unroll
            for (int i = 0; i < 4; i++)
                #pragma unroll
                for (int j = 0; j < 4; j++)
                    mma_tf32(acc[i][j], af[i][0], af[i][1], af[i][2], af[i][3],
                             bf[j][0], bf[j][1]);
        }
        cur++; if (cur >= NSTG) cur -= NSTG;
    }

    #pragma unroll
    for (int i = 0; i < 4; i++) {
        #pragma unroll
        for (int j = 0; j < 4; j++) {
            int r0 = by * 128 + wm + 16 * i + g;
            int col = bx * 128 + wn + 8 * j + 2 * t;
            size_t b0i = (size_t)r0 * N + col;
            size_t b1i = (size_t)(r0 + 8) * N + col;
            if (resid == nullptr) {
                *(float2*)&C[b0i] = make_float2(acc[i][j][0], acc[i][j][1]);
                *(float2*)&C[b1i] = make_float2(acc[i][j][2], acc[i][j][3]);
            } else {
                int bb0 = r0 >> 10, bb1 = (r0 + 8) >> 10;
                float2 gr0 = *(const float2*)&gate[(size_t)bb0 * SIXD + col];
                float2 gr1 = *(const float2*)&gate[(size_t)bb1 * SIXD + col];
                float2 rv0 = *(const float2*)&resid[b0i];
                float2 rv1 = *(const float2*)&resid[b1i];
                *(float2*)&C[b0i] = make_float2(fmaf(gr0.x, acc[i][j][0], rv0.x),
                                                fmaf(gr0.y, acc[i][j][1], rv0.y));
                *(float2*)&C[b1i] = make_float2(fmaf(gr1.x, acc[i][j][2], rv1.x),
                                                fmaf(gr1.y, acc[i][j][3], rv1.y));
            }
        }
    }
    #undef ASI
    #undef BSI
}

// ---------------- tensor-core flash attention (full branches) ----------------
// Output O written in k-permuted layout (feeds Wo GEMM).
#define ATT_PS   0
#define ATT_KS   8704
#define ATT_VS   13056
#define ATT_SMEM_BYTES ((8704 + 4352 + 4608) * 4)

__global__ __launch_bounds__(256) void attn_tc_k(const float* __restrict__ Q,
                                                 const float* __restrict__ Km,
                                                 const float* __restrict__ Vm,
                                                 float* __restrict__ O, int branch) {
    extern __shared__ float smf[];
    float* Ps = smf + ATT_PS;
    float* Ks = smf + ATT_KS;
    float* Vs = smf + ATT_VS;
    int tid = threadIdx.x, lane = tid & 31, w = tid >> 5;
    int g = lane >> 2, t = lane & 3;
    int bh = blockIdx.y;
    int b = bh >> 4, h = bh & 15;
    int qb = blockIdx.x * 128;
    int headoff = h * DHc;

    #pragma unroll
    for (int i = 0; i < 8; i++) {
        int seg = tid + i * 256;
        int row = seg >> 4, c4 = (seg & 15) << 2;
        float4 v = *(const float4*)&Q[((size_t)(b * Sc + qb + row)) * Dc + headoff + c4];
        float4 cv = make_float4(to_tf32(v.x), to_tf32(v.y), to_tf32(v.z), to_tf32(v.w));
        *(float4*)&Ps[row * 68 + c4] = cv;
    }
    __syncthreads();

    int r0 = w * 16 + g;
    uint32_t qa[8][4];
    #pragma unroll
    for (int kk = 0; kk < 8; kk++) {
        qa[kk][0] = __float_as_uint(Ps[r0 * 68 + kk * 8 + t]);
        qa[kk][1] = __float_as_uint(Ps[(r0 + 8) * 68 + kk * 8 + t]);
        qa[kk][2] = __float_as_uint(Ps[r0 * 68 + kk * 8 + t + 4]);
        qa[kk][3] = __float_as_uint(Ps[(r0 + 8) * 68 + kk * 8 + t + 4]);
    }

    float m0 = -INFINITY, m1 = -INFINITY, l0 = 0.f, l1 = 0.f;
    float o[8][4];
    #pragma unroll
    for (int j = 0; j < 8; j++)
        #pragma unroll
        for (int r = 0; r < 4; r++) o[j][r] = 0.f;

    int qi0 = qb + r0, qi1 = qi0 + 8;

    for (int kt = 0; kt < Sc; kt += 64) {
        __syncthreads();
        #pragma unroll
        for (int i = 0; i < 4; i++) {
            int seg = tid + i * 256;
            int row = seg >> 4, c4 = (seg & 15) << 2;
            size_t gi = ((size_t)(b * Sc + kt + row)) * Dc + headoff + c4;
            float4 kv = *(const float4*)&Km[gi];
            float4 vv = *(const float4*)&Vm[gi];
            *(float4*)&Ks[row * 68 + c4] =
                make_float4(to_tf32(kv.x), to_tf32(kv.y), to_tf32(kv.z), to_tf32(kv.w));
            *(float4*)&Vs[row * 72 + c4] =
                make_float4(to_tf32(vv.x), to_tf32(vv.y), to_tf32(vv.z), to_tf32(vv.w));
        }
        __syncthreads();

        float sc[8][4];
        #pragma unroll
        for (int jn = 0; jn < 8; jn++)
            #pragma unroll
            for (int r = 0; r < 4; r++) sc[jn][r] = 0.f;
        #pragma unroll
        for (int kk = 0; kk < 8; kk++) {
            #pragma unroll
            for (int jn = 0; jn < 8; jn++) {
                uint32_t b0 = __float_as_uint(Ks[(jn * 8 + g) * 68 + kk * 8 + t]);
                uint32_t b1 = __float_as_uint(Ks[(jn * 8 + g) * 68 + kk * 8 + t + 4]);
                mma_tf32(sc[jn], qa[kk][0], qa[kk][1], qa[kk][2], qa[kk][3], b0, b1);
            }
        }

        float rm0 = m0, rm1 = m1;
        #pragma unroll
        for (int jn = 0; jn < 8; jn++) {
            int kj = kt + jn * 8 + 2 * t;
            float b00 = 0.f, b01 = 0.f, b10 = 0.f, b11 = 0.f;
            if (branch == 0) {
                b00 = -(float)abs(qi0 - kj);     b01 = -(float)abs(qi0 - kj - 1);
                b10 = -(float)abs(qi1 - kj);     b11 = -(float)abs(qi1 - kj - 1);
            }
            sc[jn][0] = fmaf(sc[jn][0], 0.125f, b00);
            sc[jn][1] = fmaf(sc[jn][1], 0.125f, b01);
            sc[jn][2] = fmaf(sc[jn][2], 0.125f, b10);
            sc[jn][3] = fmaf(sc[jn][3], 0.125f, b11);
            rm0 = fmaxf(rm0, fmaxf(sc[jn][0], sc[jn][1]));
            rm1 = fmaxf(rm1, fmaxf(sc[jn][2], sc[jn][3]));
        }
        rm0 = fmaxf(rm0, __shfl_xor_sync(~0u, rm0, 1));
        rm0 = fmaxf(rm0, __shfl_xor_sync(~0u, rm0, 2));
        rm1 = fmaxf(rm1, __shfl_xor_sync(~0u, rm1, 1));
        rm1 = fmaxf(rm1, __shfl_xor_sync(~0u, rm1, 2));
        float corr0 = __expf(m0 - rm0), corr1 = __expf(m1 - rm1);
        m0 = rm0; m1 = rm1;

        float sum0 = 0.f, sum1 = 0.f;
        #pragma unroll
        for (int jn = 0; jn < 8; jn++) {
            float p0 = __expf(sc[jn][0] - m0), p1 = __expf(sc[jn][1] - m0);
            float p2 = __expf(sc[jn][2] - m1), p3 = __expf(sc[jn][3] - m1);
            sum0 += p0 + p1; sum1 += p2 + p3;
            *(float2*)&Ps[r0 * 68 + jn * 8 + 2 * t] =
                make_float2(to_tf32(p0), to_tf32(p1));
            *(float2*)&Ps[(r0 + 8) * 68 + jn * 8 + 2 * t] =
                make_float2(to_tf32(p2), to_tf32(p3));
        }
        sum0 += __shfl_xor_sync(~0u, sum0, 1);
        sum0 += __shfl_xor_sync(~0u, sum0, 2);
        sum1 += __shfl_xor_sync(~0u, sum1, 1);
        sum1 += __shfl_xor_sync(~0u, sum1, 2);
        l0 = fmaf(l0, corr0, sum0);
        l1 = fmaf(l1, corr1, sum1);
        #pragma unroll
        for (int jd = 0; jd < 8; jd++) {
            o[jd][0] *= corr0; o[jd][1] *= corr0;
            o[jd][2] *= corr1; o[jd][3] *= corr1;
        }
        __syncwarp();

        #pragma unroll
        for (int ks = 0; ks < 8; ks++) {
            uint32_t pa0 = __float_as_uint(Ps[r0 * 68 + ks * 8 + t]);
            uint32_t pa1 = __float_as_uint(Ps[(r0 + 8) * 68 + ks * 8 + t]);
            uint32_t pa2 = __float_as_uint(Ps[r0 * 68 + ks * 8 + t + 4]);
            uint32_t pa3 = __float_as_uint(Ps[(r0 + 8) * 68 + ks * 8 + t + 4]);
            #pragma unroll
            for (int jd = 0; jd < 8; jd++) {
                uint32_t vb0 = __float_as_uint(Vs[(ks * 8 + t) * 72 + jd * 8 + g]);
                uint32_t vb1 = __float_as_uint(Vs[(ks * 8 + t + 4) * 72 + jd * 8 + g]);
                mma_tf32(o[jd], pa0, pa1, pa2, pa3, vb0, vb1);
            }
        }
    }

    float inv0 = 1.f / l0, inv1 = 1.f / l1;
    size_t row0g = ((size_t)(b * Sc + qb + r0)) * Dc + headoff;
    size_t row1g = row0g + (size_t)8 * Dc;
    // permuted-column scatter (feeds k-permuted Wo GEMM)
    int cp0 = KPERM8(2 * t);        // perm position of col 2t within 8-block
    int cp1 = KPERM8(2 * t + 1);
    #pragma unroll
    for (int jd = 0; jd < 8; jd++) {
        int cb = jd * 8;
        O[row0g + cb + cp0] = o[jd][0] * inv0;
        O[row0g + cb + cp1] = o[jd][1] * inv0;
        O[row1g + cb + cp0] = o[jd][2] * inv1;
        O[row1g + cb + cp1] = o[jd][3] * inv1;
    }
}

// ---------------- sparse attention for masked branches ----------------
// Output written in k-permuted layout.
__global__ __launch_bounds__(128) void attn_sparse_k(const float* __restrict__ Q,
                                                     const float* __restrict__ Km,
                                                     const float* __restrict__ Vm,
                                                     float* __restrict__ O, int mode) {
    int w = threadIdx.x >> 5, lane = threadIdx.x & 31;
    int qi = blockIdx.x * 4 + w;
    int bh = blockIdx.y;
    int b = bh >> 4, h = bh & 15;
    size_t rowbase = ((size_t)(b * Sc + qi)) * Dc + (size_t)h * DHc;
    float q0 = Q[rowbase + lane], q1 = Q[rowbase + 32 + lane];

    int k0i, nk;
    if (mode == 1) {
        k0i = qi - 1; nk = 3;
        if (qi == 0)      { k0i = 0; nk = 2; }
        if (qi == Sc - 1) { nk = 2; }
    } else {
        k0i = qi & ~1; nk = 2;
    }

    float s[3] = {0.f, 0.f, 0.f};
    #pragma unroll 3
    for (int kk = 0; kk < 3; kk++) {
        if (kk < nk) {
            size_t kb = ((size_t)(b * Sc + k0i + kk)) * Dc + (size_t)h * DHc;
            float acc = fmaf(q0, Km[kb + lane], q1 * Km[kb + 32 + lane]);
            #pragma unroll
            for (int off = 16; off; off >>= 1)
                acc += __shfl_xor_sync(~0u, acc, off);
            s[kk] = acc * 0.125f;
        }
    }
    float mx = s[0];
    for (int kk = 1; kk < nk; kk++) mx = fmaxf(mx, s[kk]);
    float p[3], l = 0.f;
    for (int kk = 0; kk < nk; kk++) { p[kk] = __expf(s[kk] - mx); l += p[kk]; }
    float inv = 1.f / l;

    float o0 = 0.f, o1 = 0.f;
    #pragma unroll 3
    for (int kk = 0; kk < 3; kk++) {
        if (kk < nk) {
            size_t vb = ((size_t)(b * Sc + k0i + kk)) * Dc + (size_t)h * DHc;
            o0 = fmaf(p[kk], Vm[vb + lane], o0);
            o1 = fmaf(p[kk], Vm[vb + 32 + lane], o1);
        }
    }
    int lp = KPERM8(lane);
    O[rowbase + lp]      = o0 * inv;
    O[rowbase + 32 + lp] = o1 * inv;
}

// ---------------- fusion gate ----------------
__global__ __launch_bounds__(256) void gate_k(const float* __restrict__ Ob,
                                              const float* __restrict__ wg,
                                              const float* __restrict__ bg,
                                              float* __restrict__ gate) {
    int t = blockIdx.x, tid = threadIdx.x;
    float4 acc = make_float4(0.f, 0.f, 0.f, 0.f);
    for (int d = tid; d < 4 * Dc; d += 256) {
        int p = d >> 10, dd = d & 1023;
        float v = Ob[((size_t)p * TOK + t) * Dc + dd];
        float4 wv = *(const float4*)&wg[(size_t)d * 4];
        acc.x = fmaf(v, wv.x, acc.x);
        acc.y = fmaf(v, wv.y, acc.y);
        acc.z = fmaf(v, wv.z, acc.z);
        acc.w = fmaf(v, wv.w, acc.w);
    }
    #pragma unroll
    for (int off = 16; off; off >>= 1) {
        acc.x += __shfl_xor_sync(~0u, acc.x, off);
        acc.y += __shfl_xor_sync(~0u, acc.y, off);
        acc.z += __shfl_xor_sync(~0u, acc.z, off);
        acc.w += __shfl_xor_sync(~0u, acc.w, off);
    }
    __shared__ float4 red[8];
    if ((tid & 31) == 0) red[tid >> 5] = acc;
    __syncthreads();
    if (tid == 0) {
        float4 a = red[0];
        #pragma unroll
        for (int i = 1; i < 8; i++) {
            a.x += red[i].x; a.y += red[i].y; a.z += red[i].z; a.w += red[i].w;
        }
        float l0 = a.x + bg[0], l1 = a.y + bg[1], l2 = a.z + bg[2], l3 = a.w + bg[3];
        float mx = fmaxf(fmaxf(l0, l1), fmaxf(l2, l3));
        float e0 = __expf(l0 - mx), e1 = __expf(l1 - mx),
              e2 = __expf(l2 - mx), e3 = __expf(l3 - mx);
        float inv = 1.f / (e0 + e1 + e2 + e3);
        gate[t * 4 + 0] = e0 * inv; gate[t * 4 + 1] = e1 * inv;
        gate[t * 4 + 2] = e2 * inv; gate[t * 4 + 3] = e3 * inv;
    }
}

// out written k-permuted (feeds fus GEMM)
__global__ void fusemix_k(const float* __restrict__ Ob,
                          const float* __restrict__ gate,
                          float* __restrict__ out) {
    int idx = blockIdx.x * 256 + threadIdx.x;
    int t = idx >> 10;
    float g0 = gate[t * 4 + 0], g1 = gate[t * 4 + 1];
    float g2 = gate[t * 4 + 2], g3 = gate[t * 4 + 3];
    const size_t P = TOKD;
    out[KPERM8(idx)] = to_tf32(g0 * Ob[idx] + g1 * Ob[idx + P] +
                               g2 * Ob[idx + 2 * P] + g3 * Ob[idx + 3 * P]);
}

// in-place SwiGLU with in-thread 8-element k-permute (race-free)
__global__ __launch_bounds__(256) void swiglu_k(float* __restrict__ h1,
                                                const float* __restrict__ h3) {
    size_t i8 = ((size_t)blockIdx.x * 256 + threadIdx.x) * 8;
    float4 a0 = *(const float4*)&h1[i8];
    float4 a1 = *(const float4*)&h1[i8 + 4];
    float4 c0 = *(const float4*)&h3[i8];
    float4 c1 = *(const float4*)&h3[i8 + 4];
    float v0 = to_tf32((a0.x / (1.f + __expf(-a0.x))) * c0.x);
    float v1 = to_tf32((a0.y / (1.f + __expf(-a0.y))) * c0.y);
    float v2 = to_tf32((a0.z / (1.f + __expf(-a0.z))) * c0.z);
    float v3 = to_tf32((a0.w / (1.f + __expf(-a0.w))) * c0.w);
    float v4 = to_tf32((a1.x / (1.f + __expf(-a1.x))) * c1.x);
    float v5 = to_tf32((a1.y / (1.f + __expf(-a1.y))) * c1.y);
    float v6 = to_tf32((a1.z / (1.f + __expf(-a1.z))) * c1.z);
    float v7 = to_tf32((a1.w / (1.f + __expf(-a1.w))) * c1.w);
    // perm positions 0..7 hold orig k 0,4,1,5,2,6,3,7
    *(float4*)&h1[i8]     = make_float4(v0, v4, v1, v5);
    *(float4*)&h1[i8 + 4] = make_float4(v2, v6, v3, v7);
}

// ---------------- host launch ----------------
extern "C" void kernel_launch(void* const* d_in, const int* in_sizes, int n_in,
                              void* d_out, int out_size) {
    const float* x      = (const float*)d_in[0];
    const float* t_emb  = (const float*)d_in[1];
    const float* ln1_g  = (const float*)d_in[2];
    const float* ln1_b  = (const float*)d_in[3];
    const float* ln2_g  = (const float*)d_in[4];
    const float* ln2_b  = (const float*)d_in[5];
    const float* ada_w  = (const float*)d_in[6];
    const float* ada_b  = (const float*)d_in[7];

    const float *fus_wg, *fus_bg, *fus_wo, *ffn_w1, *ffn_w2, *ffn_w3;
    int ab;
    if (in_sizes[8] == 16384) {
        fus_wg = (const float*)d_in[8];  fus_bg = (const float*)d_in[9];
        fus_wo = (const float*)d_in[10];
        ffn_w1 = (const float*)d_in[11]; ffn_w2 = (const float*)d_in[12];
        ffn_w3 = (const float*)d_in[13];
        ab = 14;
    } else {
        ab = 8;
        fus_wg = (const float*)d_in[24]; fus_bg = (const float*)d_in[25];
        fus_wo = (const float*)d_in[26];
        ffn_w1 = (const float*)d_in[27]; ffn_w2 = (const float*)d_in[28];
        ffn_w3 = (const float*)d_in[29];
    }

    float *st, *ada, *nx, *wsc, *qkv, *ao4, *obr, *gate, *fused, *xmid, *hh;
    cudaGetSymbolAddress((void**)&st,    g_st);
    cudaGetSymbolAddress((void**)&ada,   g_ada);
    cudaGetSymbolAddress((void**)&nx,    g_nx);
    cudaGetSymbolAddress((void**)&wsc,   g_w);
    cudaGetSymbolAddress((void**)&qkv,   g_qkv);
    cudaGetSymbolAddress((void**)&ao4,   g_ao4);
    cudaGetSymbolAddress((void**)&obr,   g_obr);
    cudaGetSymbolAddress((void**)&gate,  g_gate);
    cudaGetSymbolAddress((void**)&fused, g_fused);
    cudaGetSymbolAddress((void**)&xmid,  g_xmid);
    cudaGetSymbolAddress((void**)&hh,    g_h);
    float* h1 = hh;
    float* h3 = hh + TOKF;

    cudaFuncSetAttribute(attn_tc_k, cudaFuncAttributeMaxDynamicSharedMemorySize,
                         ATT_SMEM_BYTES);
    cudaFuncSetAttribute(gemm_tc, cudaFuncAttributeMaxDynamicSharedMemorySize,
                         GEMM_SMEM);

    float* out = (float*)d_out;

    // 0. transpose + round + permute all GEMM weights -> [N][Kp]
    TP17 tp;
    for (int p = 0; p < 4; p++) {
        tp.p[p * 3 + 0] = (const float*)d_in[ab + p * 4 + 0];
        tp.p[p * 3 + 1] = (const float*)d_in[ab + p * 4 + 1];
        tp.p[p * 3 + 2] = (const float*)d_in[ab + p * 4 + 2];
        tp.p[12 + p]    = (const float*)d_in[ab + p * 4 + 3];
    }
    tp.p[16] = fus_wo;
    wtrans17_k<<<dim3(32, 32, 17), 256>>>(tp, wsc);
    wtrans_k<<<dim3(128, 32), 256>>>(ffn_w1, wsc + W1, Dc, Fc);   // -> [4096][1024p]
    wtrans_k<<<dim3(128, 32), 256>>>(ffn_w3, wsc + W3, Dc, Fc);
    wtrans_k<<<dim3(32, 128), 256>>>(ffn_w2, wsc + W2, Fc, Dc);   // -> [1024][4096p]

    // 1. AdaLN parameters
    silu_k<<<(Bc * Dc + 255) / 256, 256>>>(t_emb, st, Bc * Dc);
    ada_k<<<(Bc * SIXD) / 8, 256>>>(st, ada_w, ada_b, ada);

    // 2. nx = modulated LN(x), permuted + rounded
    ln_mod_k<<<TOK, 256>>>(x, ln1_g, ln1_b, ada, 0, Dc, nx);

    // 3. all 12 QKV projections in one batched launch
    dim3 gQKV(Dc / 128, TOK / 128, 12);
    gemm_tc<<<gQKV, 256, GEMM_SMEM>>>(nx, 0, wsc + WQKV, (size_t)1 << 20,
                                      qkv, TOKD, TOK, Dc, Dc, nullptr, nullptr);

    // 4. four attention branches
    dim3 gAttn(Sc / 128, Bc * Hc);
    dim3 gSparse(Sc / 4, Bc * Hc);
    for (int p = 0; p < 4; p++) {
        const float* q = qkv + (size_t)(3 * p + 0) * TOKD;
        const float* k = qkv + (size_t)(3 * p + 1) * TOKD;
        const float* v = qkv + (size_t)(3 * p + 2) * TOKD;
        float* ao = ao4 + (size_t)p * TOKD;
        if (p == 1 || p == 2)
            attn_sparse_k<<<gSparse, 128>>>(q, k, v, ao, p);
        else
            attn_tc_k<<<gAttn, 256, ATT_SMEM_BYTES>>>(q, k, v, ao, p);
    }

    // 5. four Wo GEMMs batched
    dim3 gWo(Dc / 128, TOK / 128, 4);
    gemm_tc<<<gWo, 256, GEMM_SMEM>>>(ao4, TOKD, wsc + WO, (size_t)1 << 20,
                                     obr, TOKD, TOK, Dc, Dc, nullptr, nullptr);

    // 6. learned fusion + first residual (g_m at 2D)
    dim3 gProj(Dc / 128, TOK / 128, 1);
    gate_k<<<TOK, 256>>>(obr, fus_wg, fus_bg, gate);
    fusemix_k<<<(TOK * Dc) / 256, 256>>>(obr, gate, fused);
    gemm_tc<<<gProj, 256, GEMM_SMEM>>>(fused, 0, wsc + WFUS, 0, xmid, 0,
                                       TOK, Dc, Dc, x, ada + 2 * Dc);

    // 7. FFN with AdaLN
    ln_mod_k<<<TOK, 256>>>(xmid, ln2_g, ln2_b, ada, 3 * Dc, 4 * Dc, nx);
    dim3 gFfnUp(Fc / 128, TOK / 128, 2);
    gemm_tc<<<gFfnUp, 256, GEMM_SMEM>>>(nx, 0, wsc + W1, W3 - W1,
                                        h1, TOKF, TOK, Fc, Dc, nullptr, nullptr);
    swiglu_k<<<(unsigned)(TOKF / 2048), 256>>>(h1, h3);
    gemm_tc<<<gProj, 256, GEMM_SMEM>>>(h1, 0, wsc + W2, 0, out, 0,
                                       TOK, Dc, Fc, xmid, ada + 5 * Dc);
}

// round 8
// speedup vs baseline: 1.0383x; 1.0383x over previous
#include <cuda_runtime.h>
#include <cuda_fp16.h>
#include <math.h>
#include <stdint.h>

// Problem constants
#define Bc   4
#define Sc   1024
#define Dc   1024
#define Hc   16
#define DHc  64
#define Fc   4096
#define TOK  4096          // B*S
#define SIXD 6144          // 6*D
#define TOKD ((size_t)TOK * Dc)   // 4M
#define TOKF ((size_t)TOK * Fc)   // 16M

// ---------------- scratch (no allocations allowed) ----------------
__device__ float  g_st[Bc * Dc];
__device__ float  g_ada[Bc * SIXD];
__device__ __half g_wh[(size_t)29 << 20];    // transposed fp16 weights [N][K]
__device__ __half g_nxh[TOK * Dc];           // fp16 modulated LN output
__device__ float  g_qkv[12 * TOK * Dc];      // q,k,v fp32 (GEMM out)
__device__ __half g_ao4h[4 * TOK * Dc];      // attention outputs fp16
__device__ float  g_obr[4 * TOK * Dc];       // branch outputs fp32
__device__ float  g_gate[TOK * 4];
__device__ __half g_fusedh[TOK * Dc];        // fp16
__device__ float  g_xmid[TOK * Dc];
__device__ float  g_h[2 * TOK * Fc];         // h1, h3 fp32 (GEMM out)
__device__ __half g_h1h[TOK * Fc];           // fp16 swiglu output

// weight scratch offsets (elements)
#define WQKV 0
#define WO   ((size_t)12 << 20)
#define WFUS ((size_t)16 << 20)
#define W1   ((size_t)17 << 20)
#define W3   ((size_t)21 << 20)
#define W2   ((size_t)25 << 20)

// ---------------- ptx helpers ----------------
__device__ __forceinline__ float to_tf32(float x) {
    float r;
    asm("cvt.rna.tf32.f32 %0, %1;" : "=f"(r) : "f"(x));
    return r;
}
__device__ __forceinline__ void mma_tf32(float* c, uint32_t a0, uint32_t a1,
                                         uint32_t a2, uint32_t a3,
                                         uint32_t b0, uint32_t b1) {
    asm("mma.sync.aligned.m16n8k8.row.col.f32.tf32.tf32.f32 "
        "{%0,%1,%2,%3},{%4,%5,%6,%7},{%8,%9},{%0,%1,%2,%3};"
        : "+f"(c[0]), "+f"(c[1]), "+f"(c[2]), "+f"(c[3])
        : "r"(a0), "r"(a1), "r"(a2), "r"(a3), "r"(b0), "r"(b1));
}
__device__ __forceinline__ void mma_f16(float* c, uint32_t a0, uint32_t a1,
                                        uint32_t a2, uint32_t a3,
                                        uint32_t b0, uint32_t b1) {
    asm("mma.sync.aligned.m16n8k16.row.col.f32.f16.f16.f32 "
        "{%0,%1,%2,%3},{%4,%5,%6,%7},{%8,%9},{%0,%1,%2,%3};"
        : "+f"(c[0]), "+f"(c[1]), "+f"(c[2]), "+f"(c[3])
        : "r"(a0), "r"(a1), "r"(a2), "r"(a3), "r"(b0), "r"(b1));
}
__device__ __forceinline__ void cp16(void* smem, const void* g) {
    uint32_t s = (uint32_t)__cvta_generic_to_shared(smem);
    asm volatile("cp.async.cg.shared.global [%0], [%1], 16;" :: "r"(s), "l"(g));
}
__device__ __forceinline__ void cp_commit() {
    asm volatile("cp.async.commit_group;");
}
template <int N>
__device__ __forceinline__ void cp_wait() {
    asm volatile("cp.async.wait_group %0;" :: "n"(N));
}

// ---------------- weight transpose to fp16 [N][K] ----------------
// in: W[Kd][Nd] fp32 row-major -> out: Wt[Nd][Kd] fp16
__global__ __launch_bounds__(256) void wtrans_k(const float* __restrict__ in,
                                                __half* __restrict__ out,
                                                int Kd, int Nd) {
    __shared__ float tile[32][33];
    int n0 = blockIdx.x * 32, k0 = blockIdx.y * 32;
    int tx = threadIdx.x & 31, ty = threadIdx.x >> 5;   // 32 x 8
    #pragma unroll
    for (int i = 0; i < 32; i += 8)
        tile[ty + i][tx] = in[(size_t)(k0 + ty + i) * Nd + n0 + tx];
    __syncthreads();
    #pragma unroll
    for (int i = 0; i < 32; i += 8)
        out[(size_t)(n0 + ty + i) * Kd + k0 + tx] = __float2half_rn(tile[tx][ty + i]);
}

struct TP17 { const float* p[17]; };
__global__ __launch_bounds__(256) void wtrans17_k(TP17 tp, __half* __restrict__ out) {
    __shared__ float tile[32][33];
    const float* in = tp.p[blockIdx.z];
    __half* o = out + ((size_t)blockIdx.z << 20);
    int n0 = blockIdx.x * 32, k0 = blockIdx.y * 32;
    int tx = threadIdx.x & 31, ty = threadIdx.x >> 5;
    #pragma unroll
    for (int i = 0; i < 32; i += 8)
        tile[ty + i][tx] = in[(size_t)(k0 + ty + i) * Dc + n0 + tx];
    __syncthreads();
    #pragma unroll
    for (int i = 0; i < 32; i += 8)
        o[(size_t)(n0 + ty + i) * Dc + k0 + tx] = __float2half_rn(tile[tx][ty + i]);
}

// ---------------- elementwise helpers ----------------
__global__ void silu_k(const float* __restrict__ in, float* __restrict__ out, int n) {
    int i = blockIdx.x * blockDim.x + threadIdx.x;
    if (i < n) { float v = in[i]; out[i] = v / (1.f + __expf(-v)); }
}

__global__ __launch_bounds__(256) void ada_k(const float* __restrict__ st,
                                             const float* __restrict__ W,
                                             const float* __restrict__ bias,
                                             float* __restrict__ out) {
    int o = blockIdx.x * 8 + (threadIdx.x >> 5);
    int lane = threadIdx.x & 31;
    int b = o / SIXD, n = o - b * SIXD;
    float acc = 0.f;
    for (int k = lane; k < Dc; k += 32)
        acc = fmaf(st[b * Dc + k], W[(size_t)k * SIXD + n], acc);
    #pragma unroll
    for (int off = 16; off; off >>= 1) acc += __shfl_xor_sync(~0u, acc, off);
    if (!lane) out[o] = acc + bias[n];
}

// nx = fp16( (LN(x)*g+b)*(1+sc)+sh )
__global__ __launch_bounds__(256) void ln_mod_k(const float* __restrict__ X,
                                                const float* __restrict__ gam,
                                                const float* __restrict__ bet,
                                                const float* __restrict__ ada,
                                                int sh_off, int sc_off,
                                                __half* __restrict__ out) {
    int t = blockIdx.x;
    int b = t >> 10;
    int tid = threadIdx.x;
    const float* xr = X + (size_t)t * Dc;
    float s = 0.f, ss = 0.f;
    for (int i = tid; i < Dc; i += 256) { float v = xr[i]; s += v; ss = fmaf(v, v, ss); }
    __shared__ float r1[8], r2[8];
    __shared__ float muS, rsS;
    #pragma unroll
    for (int off = 16; off; off >>= 1) {
        s  += __shfl_xor_sync(~0u, s,  off);
        ss += __shfl_xor_sync(~0u, ss, off);
    }
    if ((tid & 31) == 0) { r1[tid >> 5] = s; r2[tid >> 5] = ss; }
    __syncthreads();
    if (tid < 32) {
        float a = (tid < 8) ? r1[tid] : 0.f;
        float c = (tid < 8) ? r2[tid] : 0.f;
        #pragma unroll
        for (int off = 4; off; off >>= 1) {
            a += __shfl_xor_sync(~0u, a, off);
            c += __shfl_xor_sync(~0u, c, off);
        }
        if (tid == 0) {
            float mu = a * (1.f / Dc);
            float var = c * (1.f / Dc) - mu * mu;
            muS = mu; rsS = rsqrtf(var + 1e-6f);
        }
    }
    __syncthreads();
    float mu = muS, rs = rsS;
    const float* ar = ada + b * SIXD;
    __half* orow = out + (size_t)t * Dc;
    for (int i = tid; i < Dc; i += 256) {
        float v = (xr[i] - mu) * rs * gam[i] + bet[i];
        orow[i] = __float2half_rn(fmaf(v, 1.f + ar[sc_off + i], ar[sh_off + i]));
    }
}

// ---------------- FP16 TC GEMM: 128x128 tile, m16n8k16, 3-stage ----------------
// C = A[M,K] @ W[K,N] with Bt = W^T stored [N][K] fp16. A fp16 [M][K]. C fp32.
// resid != nullptr: C[t,n] = resid[t,n] + gate[(t>>10)*SIXD + n] * acc
#define RS   40                      // row stride in halves (80 B, 16B-aligned)
#define ASZh (128 * RS)              // 5120 halves per matrix per stage
#define STGh (2 * ASZh)              // 10240 halves per stage
#define NSTG 3
#define GEMM_SMEM (NSTG * STGh * 2)  // 61440 B

__global__ __launch_bounds__(256, 2) void gemm_tc(
    const __half* __restrict__ A, size_t azs,
    const __half* __restrict__ Bt, size_t bzs,
    float* __restrict__ C, size_t czs,
    int M, int N, int K,
    const float* __restrict__ resid, const float* __restrict__ gate) {
    extern __shared__ char smraw[];
    __half* smh = (__half*)smraw;

    A += azs * blockIdx.z; Bt += bzs * blockIdx.z; C += czs * blockIdx.z;

    int tid = threadIdx.x;
    int bx = blockIdx.x, by = blockIdx.y;
    int w = tid >> 5, lane = tid & 31;
    int wm = (w >> 2) * 64, wn = (w & 3) * 32;
    int g = lane >> 2, t = lane & 3;

    float acc[4][4][4];
    #pragma unroll
    for (int i = 0; i < 4; i++)
        #pragma unroll
        for (int j = 0; j < 4; j++)
            #pragma unroll
            for (int r = 0; r < 4; r++) acc[i][j][r] = 0.f;

    const __half* Ag = A + (size_t)(by * 128) * K;
    const __half* Bg = Bt + (size_t)(bx * 128) * K;

    int r0 = tid >> 2;                // 0..63
    int p8 = (tid & 3) * 8;           // half offset of 16B granule

    auto load_stage = [&](int st, int k0) {
        __half* As = smh + st * STGh;
        __half* Bs = As + ASZh;
        cp16(As + r0 * RS + p8,        Ag + (size_t)r0 * K + k0 + p8);
        cp16(As + (r0 + 64) * RS + p8, Ag + (size_t)(r0 + 64) * K + k0 + p8);
        cp16(Bs + r0 * RS + p8,        Bg + (size_t)r0 * K + k0 + p8);
        cp16(Bs + (r0 + 64) * RS + p8, Bg + (size_t)(r0 + 64) * K + k0 + p8);
    };

    load_stage(0, 0);  cp_commit();
    load_stage(1, 32); cp_commit();
    int cur = 0;
    int nch = K >> 5;

    for (int c = 0; c < nch; c++) {
        cp_wait<1>();
        __syncthreads();
        if (c + 2 < nch) {
            int nst = cur + 2; if (nst >= NSTG) nst -= NSTG;
            load_stage(nst, (c + 2) * 32);
        }
        cp_commit();

        const __half* Ab = smh + cur * STGh;
        const __half* Bb = Ab + ASZh;
        #pragma unroll
        for (int ks = 0; ks < 32; ks += 16) {
            int kb = ks + 2 * t;
            uint32_t af[4][4], bf[4][2];
            #pragma unroll
            for (int i = 0; i < 4; i++) {
                int m0 = wm + 16 * i + g;
                af[i][0] = *(const uint32_t*)(Ab + m0 * RS + kb);
                af[i][1] = *(const uint32_t*)(Ab + (m0 + 8) * RS + kb);
                af[i][2] = *(const uint32_t*)(Ab + m0 * RS + kb + 8);
                af[i][3] = *(const uint32_t*)(Ab + (m0 + 8) * RS + kb + 8);
            }
            #pragma unroll
            for (int j = 0; j < 4; j++) {
                int n0 = wn + 8 * j + g;
                bf[j][0] = *(const uint32_t*)(Bb + n0 * RS + kb);
                bf[j][1] = *(const uint32_t*)(Bb + n0 * RS + kb + 8);
            }
            #pragma unroll
            for (int i = 0; i < 4; i++)
                #pragma unroll
                for (int j = 0; j < 4; j++)
                    mma_f16(acc[i][j], af[i][0], af[i][1], af[i][2], af[i][3],
                            bf[j][0], bf[j][1]);
        }
        cur++; if (cur >= NSTG) cur -= NSTG;
    }

    #pragma unroll
    for (int i = 0; i < 4; i++) {
        #pragma unroll
        for (int j = 0; j < 4; j++) {
            int row0 = by * 128 + wm + 16 * i + g;
            int col  = bx * 128 + wn + 8 * j + 2 * t;
            size_t b0i = (size_t)row0 * N + col;
            size_t b1i = (size_t)(row0 + 8) * N + col;
            if (resid == nullptr) {
                *(float2*)&C[b0i] = make_float2(acc[i][j][0], acc[i][j][1]);
                *(float2*)&C[b1i] = make_float2(acc[i][j][2], acc[i][j][3]);
            } else {
                int bb0 = row0 >> 10, bb1 = (row0 + 8) >> 10;
                float2 gr0 = *(const float2*)&gate[(size_t)bb0 * SIXD + col];
                float2 gr1 = *(const float2*)&gate[(size_t)bb1 * SIXD + col];
                float2 rv0 = *(const float2*)&resid[b0i];
                float2 rv1 = *(const float2*)&resid[b1i];
                *(float2*)&C[b0i] = make_float2(fmaf(gr0.x, acc[i][j][0], rv0.x),
                                                fmaf(gr0.y, acc[i][j][1], rv0.y));
                *(float2*)&C[b1i] = make_float2(fmaf(gr1.x, acc[i][j][2], rv1.x),
                                                fmaf(gr1.y, acc[i][j][3], rv1.y));
            }
        }
    }
}

// ---------------- tensor-core flash attention (full branches) ----------------
// Q,K,V fp32 in; output O fp16 (feeds Wo GEMM).
#define ATT_PS   0
#define ATT_KS   8704
#define ATT_VS   13056
#define ATT_SMEM_BYTES ((8704 + 4352 + 4608) * 4)

__global__ __launch_bounds__(256) void attn_tc_k(const float* __restrict__ Q,
                                                 const float* __restrict__ Km,
                                                 const float* __restrict__ Vm,
                                                 __half* __restrict__ O, int branch) {
    extern __shared__ float smf[];
    float* Ps = smf + ATT_PS;
    float* Ks = smf + ATT_KS;
    float* Vs = smf + ATT_VS;
    int tid = threadIdx.x, lane = tid & 31, w = tid >> 5;
    int g = lane >> 2, t = lane & 3;
    int bh = blockIdx.y;
    int b = bh >> 4, h = bh & 15;
    int qb = blockIdx.x * 128;
    int headoff = h * DHc;

    #pragma unroll
    for (int i = 0; i < 8; i++) {
        int seg = tid + i * 256;
        int row = seg >> 4, c4 = (seg & 15) << 2;
        float4 v = *(const float4*)&Q[((size_t)(b * Sc + qb + row)) * Dc + headoff + c4];
        float4 cv = make_float4(to_tf32(v.x), to_tf32(v.y), to_tf32(v.z), to_tf32(v.w));
        *(float4*)&Ps[row * 68 + c4] = cv;
    }
    __syncthreads();

    int r0 = w * 16 + g;
    uint32_t qa[8][4];
    #pragma unroll
    for (int kk = 0; kk < 8; kk++) {
        qa[kk][0] = __float_as_uint(Ps[r0 * 68 + kk * 8 + t]);
        qa[kk][1] = __float_as_uint(Ps[(r0 + 8) * 68 + kk * 8 + t]);
        qa[kk][2] = __float_as_uint(Ps[r0 * 68 + kk * 8 + t + 4]);
        qa[kk][3] = __float_as_uint(Ps[(r0 + 8) * 68 + kk * 8 + t + 4]);
    }

    float m0 = -INFINITY, m1 = -INFINITY, l0 = 0.f, l1 = 0.f;
    float o[8][4];
    #pragma unroll
    for (int j = 0; j < 8; j++)
        #pragma unroll
        for (int r = 0; r < 4; r++) o[j][r] = 0.f;

    int qi0 = qb + r0, qi1 = qi0 + 8;

    for (int kt = 0; kt < Sc; kt += 64) {
        __syncthreads();
        #pragma unroll
        for (int i = 0; i < 4; i++) {
            int seg = tid + i * 256;
            int row = seg >> 4, c4 = (seg & 15) << 2;
            size_t gi = ((size_t)(b * Sc + kt + row)) * Dc + headoff + c4;
            float4 kv = *(const float4*)&Km[gi];
            float4 vv = *(const float4*)&Vm[gi];
            *(float4*)&Ks[row * 68 + c4] =
                make_float4(to_tf32(kv.x), to_tf32(kv.y), to_tf32(kv.z), to_tf32(kv.w));
            *(float4*)&Vs[row * 72 + c4] =
                make_float4(to_tf32(vv.x), to_tf32(vv.y), to_tf32(vv.z), to_tf32(vv.w));
        }
        __syncthreads();

        float sc[8][4];
        #pragma unroll
        for (int jn = 0; jn < 8; jn++)
            #pragma unroll
            for (int r = 0; r < 4; r++) sc[jn][r] = 0.f;
        #pragma unroll
        for (int kk = 0; kk < 8; kk++) {
            #pragma unroll
            for (int jn = 0; jn < 8; jn++) {
                uint32_t b0 = __float_as_uint(Ks[(jn * 8 + g) * 68 + kk * 8 + t]);
                uint32_t b1 = __float_as_uint(Ks[(jn * 8 + g) * 68 + kk * 8 + t + 4]);
                mma_tf32(sc[jn], qa[kk][0], qa[kk][1], qa[kk][2], qa[kk][3], b0, b1);
            }
        }

        float rm0 = m0, rm1 = m1;
        #pragma unroll
        for (int jn = 0; jn < 8; jn++) {
            int kj = kt + jn * 8 + 2 * t;
            float b00 = 0.f, b01 = 0.f, b10 = 0.f, b11 = 0.f;
            if (branch == 0) {
                b00 = -(float)abs(qi0 - kj);     b01 = -(float)abs(qi0 - kj - 1);
                b10 = -(float)abs(qi1 - kj);     b11 = -(float)abs(qi1 - kj - 1);
            }
            sc[jn][0] = fmaf(sc[jn][0], 0.125f, b00);
            sc[jn][1] = fmaf(sc[jn][1], 0.125f, b01);
            sc[jn][2] = fmaf(sc[jn][2], 0.125f, b10);
            sc[jn][3] = fmaf(sc[jn][3], 0.125f, b11);
            rm0 = fmaxf(rm0, fmaxf(sc[jn][0], sc[jn][1]));
            rm1 = fmaxf(rm1, fmaxf(sc[jn][2], sc[jn][3]));
        }
        rm0 = fmaxf(rm0, __shfl_xor_sync(~0u, rm0, 1));
        rm0 = fmaxf(rm0, __shfl_xor_sync(~0u, rm0, 2));
        rm1 = fmaxf(rm1, __shfl_xor_sync(~0u, rm1, 1));
        rm1 = fmaxf(rm1, __shfl_xor_sync(~0u, rm1, 2));
        float corr0 = __expf(m0 - rm0), corr1 = __expf(m1 - rm1);
        m0 = rm0; m1 = rm1;

        float sum0 = 0.f, sum1 = 0.f;
        #pragma unroll
        for (int jn = 0; jn < 8; jn++) {
            float p0 = __expf(sc[jn][0] - m0), p1 = __expf(sc[jn][1] - m0);
            float p2 = __expf(sc[jn][2] - m1), p3 = __expf(sc[jn][3] - m1);
            sum0 += p0 + p1; sum1 += p2 + p3;
            *(float2*)&Ps[r0 * 68 + jn * 8 + 2 * t] =
                make_float2(to_tf32(p0), to_tf32(p1));
            *(float2*)&Ps[(r0 + 8) * 68 + jn * 8 + 2 * t] =
                make_float2(to_tf32(p2), to_tf32(p3));
        }
        sum0 += __shfl_xor_sync(~0u, sum0, 1);
        sum0 += __shfl_xor_sync(~0u, sum0, 2);
        sum1 += __shfl_xor_sync(~0u, sum1, 1);
        sum1 += __shfl_xor_sync(~0u, sum1, 2);
        l0 = fmaf(l0, corr0, sum0);
        l1 = fmaf(l1, corr1, sum1);
        #pragma unroll
        for (int jd = 0; jd < 8; jd++) {
            o[jd][0] *= corr0; o[jd][1] *= corr0;
            o[jd][2] *= corr1; o[jd][3] *= corr1;
        }
        __syncwarp();

        #pragma unroll
        for (int ks = 0; ks < 8; ks++) {
            uint32_t pa0 = __float_as_uint(Ps[r0 * 68 + ks * 8 + t]);
            uint32_t pa1 = __float_as_uint(Ps[(r0 + 8) * 68 + ks * 8 + t]);
            uint32_t pa2 = __float_as_uint(Ps[r0 * 68 + ks * 8 + t + 4]);
            uint32_t pa3 = __float_as_uint(Ps[(r0 + 8) * 68 + ks * 8 + t + 4]);
            #pragma unroll
            for (int jd = 0; jd < 8; jd++) {
                uint32_t vb0 = __float_as_uint(Vs[(ks * 8 + t) * 72 + jd * 8 + g]);
                uint32_t vb1 = __float_as_uint(Vs[(ks * 8 + t + 4) * 72 + jd * 8 + g]);
                mma_tf32(o[jd], pa0, pa1, pa2, pa3, vb0, vb1);
            }
        }
    }

    float inv0 = 1.f / l0, inv1 = 1.f / l1;
    size_t row0g = ((size_t)(b * Sc + qb + r0)) * Dc + headoff;
    size_t row1g = row0g + (size_t)8 * Dc;
    #pragma unroll
    for (int jd = 0; jd < 8; jd++) {
        int col = jd * 8 + 2 * t;
        *(__half2*)&O[row0g + col] =
            __floats2half2_rn(o[jd][0] * inv0, o[jd][1] * inv0);
        *(__half2*)&O[row1g + col] =
            __floats2half2_rn(o[jd][2] * inv1, o[jd][3] * inv1);
    }
}

// ---------------- sparse attention for masked branches (fp16 out) ----------------
__global__ __launch_bounds__(128) void attn_sparse_k(const float* __restrict__ Q,
                                                     const float* __restrict__ Km,
                                                     const float* __restrict__ Vm,
                                                     __half* __restrict__ O, int mode) {
    int w = threadIdx.x >> 5, lane = threadIdx.x & 31;
    int qi = blockIdx.x * 4 + w;
    int bh = blockIdx.y;
    int b = bh >> 4, h = bh & 15;
    size_t rowbase = ((size_t)(b * Sc + qi)) * Dc + (size_t)h * DHc;
    float q0 = Q[rowbase + lane], q1 = Q[rowbase + 32 + lane];

    int k0i, nk;
    if (mode == 1) {
        k0i = qi - 1; nk = 3;
        if (qi == 0)      { k0i = 0; nk = 2; }
        if (qi == Sc - 1) { nk = 2; }
    } else {
        k0i = qi & ~1; nk = 2;
    }

    float s[3] = {0.f, 0.f, 0.f};
    #pragma unroll 3
    for (int kk = 0; kk < 3; kk++) {
        if (kk < nk) {
            size_t kb = ((size_t)(b * Sc + k0i + kk)) * Dc + (size_t)h * DHc;
            float acc = fmaf(q0, Km[kb + lane], q1 * Km[kb + 32 + lane]);
            #pragma unroll
            for (int off = 16; off; off >>= 1)
                acc += __shfl_xor_sync(~0u, acc, off);
            s[kk] = acc * 0.125f;
        }
    }
    float mx = s[0];
    for (int kk = 1; kk < nk; kk++) mx = fmaxf(mx, s[kk]);
    float p[3], l = 0.f;
    for (int kk = 0; kk < nk; kk++) { p[kk] = __expf(s[kk] - mx); l += p[kk]; }
    float inv = 1.f / l;

    float o0 = 0.f, o1 = 0.f;
    #pragma unroll 3
    for (int kk = 0; kk < 3; kk++) {
        if (kk < nk) {
            size_t vb = ((size_t)(b * Sc + k0i + kk)) * Dc + (size_t)h * DHc;
            o0 = fmaf(p[kk], Vm[vb + lane], o0);
            o1 = fmaf(p[kk], Vm[vb + 32 + lane], o1);
        }
    }
    O[rowbase + lane]      = __float2half_rn(o0 * inv);
    O[rowbase + 32 + lane] = __float2half_rn(o1 * inv);
}

// ---------------- fusion gate ----------------
__global__ __launch_bounds__(256) void gate_k(const float* __restrict__ Ob,
                                              const float* __restrict__ wg,
                                              const float* __restrict__ bg,
                                              float* __restrict__ gate) {
    int t = blockIdx.x, tid = threadIdx.x;
    float4 acc = make_float4(0.f, 0.f, 0.f, 0.f);
    for (int d = tid; d < 4 * Dc; d += 256) {
        int p = d >> 10, dd = d & 1023;
        float v = Ob[((size_t)p * TOK + t) * Dc + dd];
        float4 wv = *(const float4*)&wg[(size_t)d * 4];
        acc.x = fmaf(v, wv.x, acc.x);
        acc.y = fmaf(v, wv.y, acc.y);
        acc.z = fmaf(v, wv.z, acc.z);
        acc.w = fmaf(v, wv.w, acc.w);
    }
    #pragma unroll
    for (int off = 16; off; off >>= 1) {
        acc.x += __shfl_xor_sync(~0u, acc.x, off);
        acc.y += __shfl_xor_sync(~0u, acc.y, off);
        acc.z += __shfl_xor_sync(~0u, acc.z, off);
        acc.w += __shfl_xor_sync(~0u, acc.w, off);
    }
    __shared__ float4 red[8];
    if ((tid & 31) == 0) red[tid >> 5] = acc;
    __syncthreads();
    if (tid == 0) {
        float4 a = red[0];
        #pragma unroll
        for (int i = 1; i < 8; i++) {
            a.x += red[i].x; a.y += red[i].y; a.z += red[i].z; a.w += red[i].w;
        }
        float l0 = a.x + bg[0], l1 = a.y + bg[1], l2 = a.z + bg[2], l3 = a.w + bg[3];
        float mx = fmaxf(fmaxf(l0, l1), fmaxf(l2, l3));
        float e0 = __expf(l0 - mx), e1 = __expf(l1 - mx),
              e2 = __expf(l2 - mx), e3 = __expf(l3 - mx);
        float inv = 1.f / (e0 + e1 + e2 + e3);
        gate[t * 4 + 0] = e0 * inv; gate[t * 4 + 1] = e1 * inv;
        gate[t * 4 + 2] = e2 * inv; gate[t * 4 + 3] = e3 * inv;
    }
}

__global__ void fusemix_k(const float* __restrict__ Ob,
                          const float* __restrict__ gate,
                          __half* __restrict__ out) {
    int idx = blockIdx.x * 256 + threadIdx.x;
    int t = idx >> 10;
    float g0 = gate[t * 4 + 0], g1 = gate[t * 4 + 1];
    float g2 = gate[t * 4 + 2], g3 = gate[t * 4 + 3];
    const size_t P = TOKD;
    out[idx] = __float2half_rn(g0 * Ob[idx] + g1 * Ob[idx + P] +
                               g2 * Ob[idx + 2 * P] + g3 * Ob[idx + 3 * P]);
}

__global__ void swiglu_k(const float* __restrict__ h1,
                         const float* __restrict__ h3,
                         __half* __restrict__ out, size_t n) {
    size_t i = (size_t)blockIdx.x * 256 + threadIdx.x;
    if (i < n) {
        float a = h1[i];
        out[i] = __float2half_rn((a / (1.f + __expf(-a))) * h3[i]);
    }
}

// ---------------- host launch ----------------
extern "C" void kernel_launch(void* const* d_in, const int* in_sizes, int n_in,
                              void* d_out, int out_size) {
    const float* x      = (const float*)d_in[0];
    const float* t_emb  = (const float*)d_in[1];
    const float* ln1_g  = (const float*)d_in[2];
    const float* ln1_b  = (const float*)d_in[3];
    const float* ln2_g  = (const float*)d_in[4];
    const float* ln2_b  = (const float*)d_in[5];
    const float* ada_w  = (const float*)d_in[6];
    const float* ada_b  = (const float*)d_in[7];

    const float *fus_wg, *fus_bg, *fus_wo, *ffn_w1, *ffn_w2, *ffn_w3;
    int ab;
    if (in_sizes[8] == 16384) {
        fus_wg = (const float*)d_in[8];  fus_bg = (const float*)d_in[9];
        fus_wo = (const float*)d_in[10];
        ffn_w1 = (const float*)d_in[11]; ffn_w2 = (const float*)d_in[12];
        ffn_w3 = (const float*)d_in[13];
        ab = 14;
    } else {
        ab = 8;
        fus_wg = (const float*)d_in[24]; fus_bg = (const float*)d_in[25];
        fus_wo = (const float*)d_in[26];
        ffn_w1 = (const float*)d_in[27]; ffn_w2 = (const float*)d_in[28];
        ffn_w3 = (const float*)d_in[29];
    }

    float  *st, *ada, *qkv, *obr, *gate, *xmid, *hh;
    __half *wh, *nxh, *ao4h, *fusedh, *h1h;
    cudaGetSymbolAddress((void**)&st,     g_st);
    cudaGetSymbolAddress((void**)&ada,    g_ada);
    cudaGetSymbolAddress((void**)&wh,     g_wh);
    cudaGetSymbolAddress((void**)&nxh,    g_nxh);
    cudaGetSymbolAddress((void**)&qkv,    g_qkv);
    cudaGetSymbolAddress((void**)&ao4h,   g_ao4h);
    cudaGetSymbolAddress((void**)&obr,    g_obr);
    cudaGetSymbolAddress((void**)&gate,   g_gate);
    cudaGetSymbolAddress((void**)&fusedh, g_fusedh);
    cudaGetSymbolAddress((void**)&xmid,   g_xmid);
    cudaGetSymbolAddress((void**)&hh,     g_h);
    cudaGetSymbolAddress((void**)&h1h,    g_h1h);
    float* h1 = hh;
    float* h3 = hh + TOKF;

    cudaFuncSetAttribute(attn_tc_k, cudaFuncAttributeMaxDynamicSharedMemorySize,
                         ATT_SMEM_BYTES);
    cudaFuncSetAttribute(gemm_tc, cudaFuncAttributeMaxDynamicSharedMemorySize,
                         GEMM_SMEM);

    float* out = (float*)d_out;

    // 0. transpose all GEMM weights to fp16 [N][K]
    TP17 tp;
    for (int p = 0; p < 4; p++) {
        tp.p[p * 3 + 0] = (const float*)d_in[ab + p * 4 + 0];
        tp.p[p * 3 + 1] = (const float*)d_in[ab + p * 4 + 1];
        tp.p[p * 3 + 2] = (const float*)d_in[ab + p * 4 + 2];
        tp.p[12 + p]    = (const float*)d_in[ab + p * 4 + 3];
    }
    tp.p[16] = fus_wo;
    wtrans17_k<<<dim3(32, 32, 17), 256>>>(tp, wh);
    wtrans_k<<<dim3(128, 32), 256>>>(ffn_w1, wh + W1, Dc, Fc);   // -> [4096][1024]
    wtrans_k<<<dim3(128, 32), 256>>>(ffn_w3, wh + W3, Dc, Fc);
    wtrans_k<<<dim3(32, 128), 256>>>(ffn_w2, wh + W2, Fc, Dc);   // -> [1024][4096]

    // 1. AdaLN parameters
    silu_k<<<(Bc * Dc + 255) / 256, 256>>>(t_emb, st, Bc * Dc);
    ada_k<<<(Bc * SIXD) / 8, 256>>>(st, ada_w, ada_b, ada);

    // 2. nx = modulated LN(x), fp16
    ln_mod_k<<<TOK, 256>>>(x, ln1_g, ln1_b, ada, 0, Dc, nxh);

    // 3. all 12 QKV projections in one batched launch
    dim3 gQKV(Dc / 128, TOK / 128, 12);
    gemm_tc<<<gQKV, 256, GEMM_SMEM>>>(nxh, 0, wh + WQKV, (size_t)1 << 20,
                                      qkv, TOKD, TOK, Dc, Dc, nullptr, nullptr);

    // 4. four attention branches (fp32 in, fp16 out)
    dim3 gAttn(Sc / 128, Bc * Hc);
    dim3 gSparse(Sc / 4, Bc * Hc);
    for (int p = 0; p < 4; p++) {
        const float* q = qkv + (size_t)(3 * p + 0) * TOKD;
        const float* k = qkv + (size_t)(3 * p + 1) * TOKD;
        const float* v = qkv + (size_t)(3 * p + 2) * TOKD;
        __half* ao = ao4h + (size_t)p * TOKD;
        if (p == 1 || p == 2)
            attn_sparse_k<<<gSparse, 128>>>(q, k, v, ao, p);
        else
            attn_tc_k<<<gAttn, 256, ATT_SMEM_BYTES>>>(q, k, v, ao, p);
    }

    // 5. four Wo GEMMs batched
    dim3 gWo(Dc / 128, TOK / 128, 4);
    gemm_tc<<<gWo, 256, GEMM_SMEM>>>(ao4h, TOKD, wh + WO, (size_t)1 << 20,
                                     obr, TOKD, TOK, Dc, Dc, nullptr, nullptr);

    // 6. learned fusion + first residual (g_m at 2D)
    dim3 gProj(Dc / 128, TOK / 128, 1);
    gate_k<<<TOK, 256>>>(obr, fus_wg, fus_bg, gate);
    fusemix_k<<<(TOK * Dc) / 256, 256>>>(obr, gate, fusedh);
    gemm_tc<<<gProj, 256, GEMM_SMEM>>>(fusedh, 0, wh + WFUS, 0, xmid, 0,
                                       TOK, Dc, Dc, x, ada + 2 * Dc);

    // 7. FFN with AdaLN
    ln_mod_k<<<TOK, 256>>>(xmid, ln2_g, ln2_b, ada, 3 * Dc, 4 * Dc, nxh);
    dim3 gFfnUp(Fc / 128, TOK / 128, 2);
    gemm_tc<<<gFfnUp, 256, GEMM_SMEM>>>(nxh, 0, wh + W1, W3 - W1,
                                        h1, TOKF, TOK, Fc, Dc, nullptr, nullptr);
    size_t nf = TOKF;
    swiglu_k<<<(unsigned)((nf + 255) / 256), 256>>>(h1, h3, h1h, nf);
    gemm_tc<<<gProj, 256, GEMM_SMEM>>>(h1h, 0, wh + W2, 0, out, 0,
                                       TOK, Dc, Fc, xmid, ada + 5 * Dc);
}

// round 9
// speedup vs baseline: 1.6888x; 1.6265x over previous
#include <cuda_runtime.h>
#include <cuda_fp16.h>
#include <math.h>
#include <stdint.h>

// Problem constants
#define Bc   4
#define Sc   1024
#define Dc   1024
#define Hc   16
#define DHc  64
#define Fc   4096
#define TOK  4096          // B*S
#define SIXD 6144          // 6*D
#define TOKD ((size_t)TOK * Dc)   // 4M
#define TOKF ((size_t)TOK * Fc)   // 16M

// ---------------- scratch (no allocations allowed) ----------------
__device__ float  g_st[Bc * Dc];
__device__ float  g_ada[Bc * SIXD];
__device__ __half g_wh[(size_t)29 << 20];    // transposed fp16 weights [N][K]
__device__ __half g_nxh[TOK * Dc];           // fp16 modulated LN output
__device__ float  g_qkv[12 * TOK * Dc];      // q,k,v fp32 (GEMM out)
__device__ __half g_ao4h[4 * TOK * Dc];      // attention outputs fp16
__device__ float  g_obr[4 * TOK * Dc];       // branch outputs fp32
__device__ float  g_gate[TOK * 4];
__device__ __half g_fusedh[TOK * Dc];        // fp16
__device__ float  g_xmid[TOK * Dc];
__device__ float  g_h[2 * TOK * Fc];         // h1, h3 fp32 (GEMM out)
__device__ __half g_h1h[TOK * Fc];           // fp16 swiglu output

// weight scratch offsets (elements)
#define WQKV 0
#define WO   ((size_t)12 << 20)
#define WFUS ((size_t)16 << 20)
#define W1   ((size_t)17 << 20)
#define W3   ((size_t)21 << 20)
#define W2   ((size_t)25 << 20)

// ---------------- ptx helpers ----------------
__device__ __forceinline__ float to_tf32(float x) {
    float r;
    asm("cvt.rna.tf32.f32 %0, %1;" : "=f"(r) : "f"(x));
    return r;
}
__device__ __forceinline__ void mma_tf32(float* c, uint32_t a0, uint32_t a1,
                                         uint32_t a2, uint32_t a3,
                                         uint32_t b0, uint32_t b1) {
    asm("mma.sync.aligned.m16n8k8.row.col.f32.tf32.tf32.f32 "
        "{%0,%1,%2,%3},{%4,%5,%6,%7},{%8,%9},{%0,%1,%2,%3};"
        : "+f"(c[0]), "+f"(c[1]), "+f"(c[2]), "+f"(c[3])
        : "r"(a0), "r"(a1), "r"(a2), "r"(a3), "r"(b0), "r"(b1));
}
__device__ __forceinline__ void mma_f16(float* c, uint32_t a0, uint32_t a1,
                                        uint32_t a2, uint32_t a3,
                                        uint32_t b0, uint32_t b1) {
    asm("mma.sync.aligned.m16n8k16.row.col.f32.f16.f16.f32 "
        "{%0,%1,%2,%3},{%4,%5,%6,%7},{%8,%9},{%0,%1,%2,%3};"
        : "+f"(c[0]), "+f"(c[1]), "+f"(c[2]), "+f"(c[3])
        : "r"(a0), "r"(a1), "r"(a2), "r"(a3), "r"(b0), "r"(b1));
}
__device__ __forceinline__ void ldsm_x4(uint32_t& r0, uint32_t& r1,
                                        uint32_t& r2, uint32_t& r3, uint32_t addr) {
    asm volatile("ldmatrix.sync.aligned.m8n8.x4.shared.b16 {%0,%1,%2,%3}, [%4];"
                 : "=r"(r0), "=r"(r1), "=r"(r2), "=r"(r3) : "r"(addr));
}
__device__ __forceinline__ void cp16s(uint32_t smem, const void* g) {
    asm volatile("cp.async.cg.shared.global [%0], [%1], 16;" :: "r"(smem), "l"(g));
}
__device__ __forceinline__ void cp_commit() {
    asm volatile("cp.async.commit_group;");
}
template <int N>
__device__ __forceinline__ void cp_wait() {
    asm volatile("cp.async.wait_group %0;" :: "n"(N));
}

// ---------------- weight transpose to fp16 [N][K] ----------------
__global__ __launch_bounds__(256) void wtrans_k(const float* __restrict__ in,
                                                __half* __restrict__ out,
                                                int Kd, int Nd) {
    __shared__ float tile[32][33];
    int n0 = blockIdx.x * 32, k0 = blockIdx.y * 32;
    int tx = threadIdx.x & 31, ty = threadIdx.x >> 5;   // 32 x 8
    #pragma unroll
    for (int i = 0; i < 32; i += 8)
        tile[ty + i][tx] = in[(size_t)(k0 + ty + i) * Nd + n0 + tx];
    __syncthreads();
    #pragma unroll
    for (int i = 0; i < 32; i += 8)
        out[(size_t)(n0 + ty + i) * Kd + k0 + tx] = __float2half_rn(tile[tx][ty + i]);
}

struct TP17 { const float* p[17]; };
__global__ __launch_bounds__(256) void wtrans17_k(TP17 tp, __half* __restrict__ out) {
    __shared__ float tile[32][33];
    const float* in = tp.p[blockIdx.z];
    __half* o = out + ((size_t)blockIdx.z << 20);
    int n0 = blockIdx.x * 32, k0 = blockIdx.y * 32;
    int tx = threadIdx.x & 31, ty = threadIdx.x >> 5;
    #pragma unroll
    for (int i = 0; i < 32; i += 8)
        tile[ty + i][tx] = in[(size_t)(k0 + ty + i) * Dc + n0 + tx];
    __syncthreads();
    #pragma unroll
    for (int i = 0; i < 32; i += 8)
        o[(size_t)(n0 + ty + i) * Dc + k0 + tx] = __float2half_rn(tile[tx][ty + i]);
}

// ---------------- elementwise helpers ----------------
__global__ void silu_k(const float* __restrict__ in, float* __restrict__ out, int n) {
    int i = blockIdx.x * blockDim.x + threadIdx.x;
    if (i < n) { float v = in[i]; out[i] = v / (1.f + __expf(-v)); }
}

__global__ __launch_bounds__(256) void ada_k(const float* __restrict__ st,
                                             const float* __restrict__ W,
                                             const float* __restrict__ bias,
                                             float* __restrict__ out) {
    int o = blockIdx.x * 8 + (threadIdx.x >> 5);
    int lane = threadIdx.x & 31;
    int b = o / SIXD, n = o - b * SIXD;
    float acc = 0.f;
    for (int k = lane; k < Dc; k += 32)
        acc = fmaf(st[b * Dc + k], W[(size_t)k * SIXD + n], acc);
    #pragma unroll
    for (int off = 16; off; off >>= 1) acc += __shfl_xor_sync(~0u, acc, off);
    if (!lane) out[o] = acc + bias[n];
}

__global__ __launch_bounds__(256) void ln_mod_k(const float* __restrict__ X,
                                                const float* __restrict__ gam,
                                                const float* __restrict__ bet,
                                                const float* __restrict__ ada,
                                                int sh_off, int sc_off,
                                                __half* __restrict__ out) {
    int t = blockIdx.x;
    int b = t >> 10;
    int tid = threadIdx.x;
    const float* xr = X + (size_t)t * Dc;
    float s = 0.f, ss = 0.f;
    for (int i = tid; i < Dc; i += 256) { float v = xr[i]; s += v; ss = fmaf(v, v, ss); }
    __shared__ float r1[8], r2[8];
    __shared__ float muS, rsS;
    #pragma unroll
    for (int off = 16; off; off >>= 1) {
        s  += __shfl_xor_sync(~0u, s,  off);
        ss += __shfl_xor_sync(~0u, ss, off);
    }
    if ((tid & 31) == 0) { r1[tid >> 5] = s; r2[tid >> 5] = ss; }
    __syncthreads();
    if (tid < 32) {
        float a = (tid < 8) ? r1[tid] : 0.f;
        float c = (tid < 8) ? r2[tid] : 0.f;
        #pragma unroll
        for (int off = 4; off; off >>= 1) {
            a += __shfl_xor_sync(~0u, a, off);
            c += __shfl_xor_sync(~0u, c, off);
        }
        if (tid == 0) {
            float mu = a * (1.f / Dc);
            float var = c * (1.f / Dc) - mu * mu;
            muS = mu; rsS = rsqrtf(var + 1e-6f);
        }
    }
    __syncthreads();
    float mu = muS, rs = rsS;
    const float* ar = ada + b * SIXD;
    __half* orow = out + (size_t)t * Dc;
    for (int i = tid; i < Dc; i += 256) {
        float v = (xr[i] - mu) * rs * gam[i] + bet[i];
        orow[i] = __float2half_rn(fmaf(v, 1.f + ar[sc_off + i], ar[sh_off + i]));
    }
}

// ---------------- FP16 TC GEMM: 128x128 tile, ldmatrix + m16n8k16 ----------------
// C = A[M,K] @ W[K,N], Bt = W^T stored [N][K] fp16, A fp16 [M][K], C fp32.
// 4-stage cp.async; 8 warps of 64x32.
// resid != nullptr: C[t,n] = resid[t,n] + gate[(t>>10)*SIXD + n] * acc
#define RS   40                      // row stride in halves (80 B)
#define ASZh (128 * RS)              // 5120 halves per matrix per stage
#define STGh (2 * ASZh)              // 10240 halves per stage
#define NSTG 4
#define STGB (STGh * 2)              // 20480 B per stage
#define GEMM_SMEM (NSTG * STGB)      // 81920 B

__global__ __launch_bounds__(256, 2) void gemm_tc(
    const __half* __restrict__ A, size_t azs,
    const __half* __restrict__ Bt, size_t bzs,
    float* __restrict__ C, size_t czs,
    int M, int N, int K,
    const float* __restrict__ resid, const float* __restrict__ gate) {
    extern __shared__ char smraw[];
    __half* smh = (__half*)smraw;
    uint32_t smbase = (uint32_t)__cvta_generic_to_shared(smraw);

    A += azs * blockIdx.z; Bt += bzs * blockIdx.z; C += czs * blockIdx.z;

    int tid = threadIdx.x;
    int bx = blockIdx.x, by = blockIdx.y;
    int w = tid >> 5, lane = tid & 31;
    int wm = (w >> 2) * 64, wn = (w & 3) * 32;
    int g = lane >> 2, t = lane & 3;
    int lm = lane & 7, lq = lane >> 3;      // ldmatrix row / matrix index

    float acc[4][4][4];
    #pragma unroll
    for (int i = 0; i < 4; i++)
        #pragma unroll
        for (int j = 0; j < 4; j++)
            #pragma unroll
            for (int r = 0; r < 4; r++) acc[i][j][r] = 0.f;

    const __half* Ag = A + (size_t)(by * 128) * K;
    const __half* Bg = Bt + (size_t)(bx * 128) * K;

    // ldmatrix per-thread byte offsets (within a stage)
    uint32_t aoff[4], boff[2];
    {
        int koff = (lq >> 1) * 8;           // halves
        int rA = lm + 8 * (lq & 1);
        #pragma unroll
        for (int i = 0; i < 4; i++)
            aoff[i] = (uint32_t)(((wm + 16 * i + rA) * RS + koff) * 2);
        #pragma unroll
        for (int jp = 0; jp < 2; jp++)
            boff[jp] = (uint32_t)((ASZh + (wn + 16 * jp + 8 * (lq & 1) + lm) * RS + koff) * 2);
    }

    int r0 = tid >> 2;                // 0..63
    int p8 = (tid & 3) * 8;           // half offset of 16B granule

    auto load_stage = [&](int st, int k0) {
        uint32_t As = smbase + st * STGB;
        uint32_t Bs = As + ASZh * 2;
        cp16s(As + (r0 * RS + p8) * 2,        Ag + (size_t)r0 * K + k0 + p8);
        cp16s(As + ((r0 + 64) * RS + p8) * 2, Ag + (size_t)(r0 + 64) * K + k0 + p8);
        cp16s(Bs + (r0 * RS + p8) * 2,        Bg + (size_t)r0 * K + k0 + p8);
        cp16s(Bs + ((r0 + 64) * RS + p8) * 2, Bg + (size_t)(r0 + 64) * K + k0 + p8);
    };

    load_stage(0, 0);  cp_commit();
    load_stage(1, 32); cp_commit();
    load_stage(2, 64); cp_commit();
    int cur = 0;
    int nch = K >> 5;

    for (int c = 0; c < nch; c++) {
        cp_wait<2>();
        __syncthreads();
        if (c + 3 < nch) {
            int nst = cur + 3; if (nst >= NSTG) nst -= NSTG;
            load_stage(nst, (c + 3) * 32);
        }
        cp_commit();

        uint32_t stb = smbase + cur * STGB;
        #pragma unroll
        for (int ks = 0; ks < 2; ks++) {          // two 16-k steps
            uint32_t kadd = stb + ks * 32;        // 16 halves = 32 B
            uint32_t af[4][4], bf[4][2];
            #pragma unroll
            for (int i = 0; i < 4; i++)
                ldsm_x4(af[i][0], af[i][1], af[i][2], af[i][3], kadd + aoff[i]);
            #pragma unroll
            for (int jp = 0; jp < 2; jp++)
                ldsm_x4(bf[2 * jp][0], bf[2 * jp + 1][0],
                        bf[2 * jp][1], bf[2 * jp + 1][1], kadd + boff[jp]);
            #pragma unroll
            for (int i = 0; i < 4; i++)
                #pragma unroll
                for (int j = 0; j < 4; j++)
                    mma_f16(acc[i][j], af[i][0], af[i][1], af[i][2], af[i][3],
                            bf[j][0], bf[j][1]);
        }
        cur++; if (cur >= NSTG) cur -= NSTG;
    }

    #pragma unroll
    for (int i = 0; i < 4; i++) {
        #pragma unroll
        for (int j = 0; j < 4; j++) {
            int row0 = by * 128 + wm + 16 * i + g;
            int col  = bx * 128 + wn + 8 * j + 2 * t;
            size_t b0i = (size_t)row0 * N + col;
            size_t b1i = (size_t)(row0 + 8) * N + col;
            if (resid == nullptr) {
                *(float2*)&C[b0i] = make_float2(acc[i][j][0], acc[i][j][1]);
                *(float2*)&C[b1i] = make_float2(acc[i][j][2], acc[i][j][3]);
            } else {
                int bb0 = row0 >> 10, bb1 = (row0 + 8) >> 10;
                float2 gr0 = *(const float2*)&gate[(size_t)bb0 * SIXD + col];
                float2 gr1 = *(const float2*)&gate[(size_t)bb1 * SIXD + col];
                float2 rv0 = *(const float2*)&resid[b0i];
                float2 rv1 = *(const float2*)&resid[b1i];
                *(float2*)&C[b0i] = make_float2(fmaf(gr0.x, acc[i][j][0], rv0.x),
                                                fmaf(gr0.y, acc[i][j][1], rv0.y));
                *(float2*)&C[b1i] = make_float2(fmaf(gr1.x, acc[i][j][2], rv1.x),
                                                fmaf(gr1.y, acc[i][j][3], rv1.y));
            }
        }
    }
}

// ---------------- tensor-core flash attention (full branches) ----------------
#define ATT_PS   0
#define ATT_KS   8704
#define ATT_VS   13056
#define ATT_SMEM_BYTES ((8704 + 4352 + 4608) * 4)

__global__ __launch_bounds__(256) void attn_tc_k(const float* __restrict__ Q,
                                                 const float* __restrict__ Km,
                                                 const float* __restrict__ Vm,
                                                 __half* __restrict__ O, int branch) {
    extern __shared__ float smf[];
    float* Ps = smf + ATT_PS;
    float* Ks = smf + ATT_KS;
    float* Vs = smf + ATT_VS;
    int tid = threadIdx.x, lane = tid & 31, w = tid >> 5;
    int g = lane >> 2, t = lane & 3;
    int bh = blockIdx.y;
    int b = bh >> 4, h = bh & 15;
    int qb = blockIdx.x * 128;
    int headoff = h * DHc;

    #pragma unroll
    for (int i = 0; i < 8; i++) {
        int seg = tid + i * 256;
        int row = seg >> 4, c4 = (seg & 15) << 2;
        float4 v = *(const float4*)&Q[((size_t)(b * Sc + qb + row)) * Dc + headoff + c4];
        float4 cv = make_float4(to_tf32(v.x), to_tf32(v.y), to_tf32(v.z), to_tf32(v.w));
        *(float4*)&Ps[row * 68 + c4] = cv;
    }
    __syncthreads();

    int r0 = w * 16 + g;
    uint32_t qa[8][4];
    #pragma unroll
    for (int kk = 0; kk < 8; kk++) {
        qa[kk][0] = __float_as_uint(Ps[r0 * 68 + kk * 8 + t]);
        qa[kk][1] = __float_as_uint(Ps[(r0 + 8) * 68 + kk * 8 + t]);
        qa[kk][2] = __float_as_uint(Ps[r0 * 68 + kk * 8 + t + 4]);
        qa[kk][3] = __float_as_uint(Ps[(r0 + 8) * 68 + kk * 8 + t + 4]);
    }

    float m0 = -INFINITY, m1 = -INFINITY, l0 = 0.f, l1 = 0.f;
    float o[8][4];
    #pragma unroll
    for (int j = 0; j < 8; j++)
        #pragma unroll
        for (int r = 0; r < 4; r++) o[j][r] = 0.f;

    int qi0 = qb + r0, qi1 = qi0 + 8;

    for (int kt = 0; kt < Sc; kt += 64) {
        __syncthreads();
        #pragma unroll
        for (int i = 0; i < 4; i++) {
            int seg = tid + i * 256;
            int row = seg >> 4, c4 = (seg & 15) << 2;
            size_t gi = ((size_t)(b * Sc + kt + row)) * Dc + headoff + c4;
            float4 kv = *(const float4*)&Km[gi];
            float4 vv = *(const float4*)&Vm[gi];
            *(float4*)&Ks[row * 68 + c4] =
                make_float4(to_tf32(kv.x), to_tf32(kv.y), to_tf32(kv.z), to_tf32(kv.w));
            *(float4*)&Vs[row * 72 + c4] =
                make_float4(to_tf32(vv.x), to_tf32(vv.y), to_tf32(vv.z), to_tf32(vv.w));
        }
        __syncthreads();

        float sc[8][4];
        #pragma unroll
        for (int jn = 0; jn < 8; jn++)
            #pragma unroll
            for (int r = 0; r < 4; r++) sc[jn][r] = 0.f;
        #pragma unroll
        for (int kk = 0; kk < 8; kk++) {
            #pragma unroll
            for (int jn = 0; jn < 8; jn++) {
                uint32_t b0 = __float_as_uint(Ks[(jn * 8 + g) * 68 + kk * 8 + t]);
                uint32_t b1 = __float_as_uint(Ks[(jn * 8 + g) * 68 + kk * 8 + t + 4]);
                mma_tf32(sc[jn], qa[kk][0], qa[kk][1], qa[kk][2], qa[kk][3], b0, b1);
            }
        }

        float rm0 = m0, rm1 = m1;
        #pragma unroll
        for (int jn = 0; jn < 8; jn++) {
            int kj = kt + jn * 8 + 2 * t;
            float b00 = 0.f, b01 = 0.f, b10 = 0.f, b11 = 0.f;
            if (branch == 0) {
                b00 = -(float)abs(qi0 - kj);     b01 = -(float)abs(qi0 - kj - 1);
                b10 = -(float)abs(qi1 - kj);     b11 = -(float)abs(qi1 - kj - 1);
            }
            sc[jn][0] = fmaf(sc[jn][0], 0.125f, b00);
            sc[jn][1] = fmaf(sc[jn][1], 0.125f, b01);
            sc[jn][2] = fmaf(sc[jn][2], 0.125f, b10);
            sc[jn][3] = fmaf(sc[jn][3], 0.125f, b11);
            rm0 = fmaxf(rm0, fmaxf(sc[jn][0], sc[jn][1]));
            rm1 = fmaxf(rm1, fmaxf(sc[jn][2], sc[jn][3]));
        }
        rm0 = fmaxf(rm0, __shfl_xor_sync(~0u, rm0, 1));
        rm0 = fmaxf(rm0, __shfl_xor_sync(~0u, rm0, 2));
        rm1 = fmaxf(rm1, __shfl_xor_sync(~0u, rm1, 1));
        rm1 = fmaxf(rm1, __shfl_xor_sync(~0u, rm1, 2));
        float corr0 = __expf(m0 - rm0), corr1 = __expf(m1 - rm1);
        m0 = rm0; m1 = rm1;

        float sum0 = 0.f, sum1 = 0.f;
        #pragma unroll
        for (int jn = 0; jn < 8; jn++) {
            float p0 = __expf(sc[jn][0] - m0), p1 = __expf(sc[jn][1] - m0);
            float p2 = __expf(sc[jn][2] - m1), p3 = __expf(sc[jn][3] - m1);
            sum0 += p0 + p1; sum1 += p2 + p3;
            *(float2*)&Ps[r0 * 68 + jn * 8 + 2 * t] =
                make_float2(to_tf32(p0), to_tf32(p1));
            *(float2*)&Ps[(r0 + 8) * 68 + jn * 8 + 2 * t] =
                make_float2(to_tf32(p2), to_tf32(p3));
        }
        sum0 += __shfl_xor_sync(~0u, sum0, 1);
        sum0 += __shfl_xor_sync(~0u, sum0, 2);
        sum1 += __shfl_xor_sync(~0u, sum1, 1);
        sum1 += __shfl_xor_sync(~0u, sum1, 2);
        l0 = fmaf(l0, corr0, sum0);
        l1 = fmaf(l1, corr1, sum1);
        #pragma unroll
        for (int jd = 0; jd < 8; jd++) {
            o[jd][0] *= corr0; o[jd][1] *= corr0;
            o[jd][2] *= corr1; o[jd][3] *= corr1;
        }
        __syncwarp();

        #pragma unroll
        for (int ks = 0; ks < 8; ks++) {
            uint32_t pa0 = __float_as_uint(Ps[r0 * 68 + ks * 8 + t]);
            uint32_t pa1 = __float_as_uint(Ps[(r0 + 8) * 68 + ks * 8 + t]);
            uint32_t pa2 = __float_as_uint(Ps[r0 * 68 + ks * 8 + t + 4]);
            uint32_t pa3 = __float_as_uint(Ps[(r0 + 8) * 68 + ks * 8 + t + 4]);
            #pragma unroll
            for (int jd = 0; jd < 8; jd++) {
                uint32_t vb0 = __float_as_uint(Vs[(ks * 8 + t) * 72 + jd * 8 + g]);
                uint32_t vb1 = __float_as_uint(Vs[(ks * 8 + t + 4) * 72 + jd * 8 + g]);
                mma_tf32(o[jd], pa0, pa1, pa2, pa3, vb0, vb1);
            }
        }
    }

    float inv0 = 1.f / l0, inv1 = 1.f / l1;
    size_t row0g = ((size_t)(b * Sc + qb + r0)) * Dc + headoff;
    size_t row1g = row0g + (size_t)8 * Dc;
    #pragma unroll
    for (int jd = 0; jd < 8; jd++) {
        int col = jd * 8 + 2 * t;
        *(__half2*)&O[row0g + col] =
            __floats2half2_rn(o[jd][0] * inv0, o[jd][1] * inv0);
        *(__half2*)&O[row1g + col] =
            __floats2half2_rn(o[jd][2] * inv1, o[jd][3] * inv1);
    }
}

// ---------------- sparse attention for masked branches (fp16 out) ----------------
__global__ __launch_bounds__(128) void attn_sparse_k(const float* __restrict__ Q,
                                                     const float* __restrict__ Km,
                                                     const float* __restrict__ Vm,
                                                     __half* __restrict__ O, int mode) {
    int w = threadIdx.x >> 5, lane = threadIdx.x & 31;
    int qi = blockIdx.x * 4 + w;
    int bh = blockIdx.y;
    int b = bh >> 4, h = bh & 15;
    size_t rowbase = ((size_t)(b * Sc + qi)) * Dc + (size_t)h * DHc;
    float q0 = Q[rowbase + lane], q1 = Q[rowbase + 32 + lane];

    int k0i, nk;
    if (mode == 1) {
        k0i = qi - 1; nk = 3;
        if (qi == 0)      { k0i = 0; nk = 2; }
        if (qi == Sc - 1) { nk = 2; }
    } else {
        k0i = qi & ~1; nk = 2;
    }

    float s[3] = {0.f, 0.f, 0.f};
    #pragma unroll 3
    for (int kk = 0; kk < 3; kk++) {
        if (kk < nk) {
            size_t kb = ((size_t)(b * Sc + k0i + kk)) * Dc + (size_t)h * DHc;
            float acc = fmaf(q0, Km[kb + lane], q1 * Km[kb + 32 + lane]);
            #pragma unroll
            for (int off = 16; off; off >>= 1)
                acc += __shfl_xor_sync(~0u, acc, off);
            s[kk] = acc * 0.125f;
        }
    }
    float mx = s[0];
    for (int kk = 1; kk < nk; kk++) mx = fmaxf(mx, s[kk]);
    float p[3], l = 0.f;
    for (int kk = 0; kk < nk; kk++) { p[kk] = __expf(s[kk] - mx); l += p[kk]; }
    float inv = 1.f / l;

    float o0 = 0.f, o1 = 0.f;
    #pragma unroll 3
    for (int kk = 0; kk < 3; kk++) {
        if (kk < nk) {
            size_t vb = ((size_t)(b * Sc + k0i + kk)) * Dc + (size_t)h * DHc;
            o0 = fmaf(p[kk], Vm[vb + lane], o0);
            o1 = fmaf(p[kk], Vm[vb + 32 + lane], o1);
        }
    }
    O[rowbase + lane]      = __float2half_rn(o0 * inv);
    O[rowbase + 32 + lane] = __float2half_rn(o1 * inv);
}

// ---------------- fusion gate ----------------
__global__ __launch_bounds__(256) void gate_k(const float* __restrict__ Ob,
                                              const float* __restrict__ wg,
                                              const float* __restrict__ bg,
                                              float* __restrict__ gate) {
    int t = blockIdx.x, tid = threadIdx.x;
    float4 acc = make_float4(0.f, 0.f, 0.f, 0.f);
    for (int d = tid; d < 4 * Dc; d += 256) {
        int p = d >> 10, dd = d & 1023;
        float v = Ob[((size_t)p * TOK + t) * Dc + dd];
        float4 wv = *(const float4*)&wg[(size_t)d * 4];
        acc.x = fmaf(v, wv.x, acc.x);
        acc.y = fmaf(v, wv.y, acc.y);
        acc.z = fmaf(v, wv.z, acc.z);
        acc.w = fmaf(v, wv.w, acc.w);
    }
    #pragma unroll
    for (int off = 16; off; off >>= 1) {
        acc.x += __shfl_xor_sync(~0u, acc.x, off);
        acc.y += __shfl_xor_sync(~0u, acc.y, off);
        acc.z += __shfl_xor_sync(~0u, acc.z, off);
        acc.w += __shfl_xor_sync(~0u, acc.w, off);
    }
    __shared__ float4 red[8];
    if ((tid & 31) == 0) red[tid >> 5] = acc;
    __syncthreads();
    if (tid == 0) {
        float4 a = red[0];
        #pragma unroll
        for (int i = 1; i < 8; i++) {
            a.x += red[i].x; a.y += red[i].y; a.z += red[i].z; a.w += red[i].w;
        }
        float l0 = a.x + bg[0], l1 = a.y + bg[1], l2 = a.z + bg[2], l3 = a.w + bg[3];
        float mx = fmaxf(fmaxf(l0, l1), fmaxf(l2, l3));
        float e0 = __expf(l0 - mx), e1 = __expf(l1 - mx),
              e2 = __expf(l2 - mx), e3 = __expf(l3 - mx);
        float inv = 1.f / (e0 + e1 + e2 + e3);
        gate[t * 4 + 0] = e0 * inv; gate[t * 4 + 1] = e1 * inv;
        gate[t * 4 + 2] = e2 * inv; gate[t * 4 + 3] = e3 * inv;
    }
}

__global__ void fusemix_k(const float* __restrict__ Ob,
                          const float* __restrict__ gate,
                          __half* __restrict__ out) {
    int idx = blockIdx.x * 256 + threadIdx.x;
    int t = idx >> 10;
    float g0 = gate[t * 4 + 0], g1 = gate[t * 4 + 1];
    float g2 = gate[t * 4 + 2], g3 = gate[t * 4 + 3];
    const size_t P = TOKD;
    out[idx] = __float2half_rn(g0 * Ob[idx] + g1 * Ob[idx + P] +
                               g2 * Ob[idx + 2 * P] + g3 * Ob[idx + 3 * P]);
}

__global__ void swiglu_k(const float* __restrict__ h1,
                         const float* __restrict__ h3,
                         __half* __restrict__ out, size_t n) {
    size_t i = (size_t)blockIdx.x * 256 + threadIdx.x;
    if (i < n) {
        float a = h1[i];
        out[i] = __float2half_rn((a / (1.f + __expf(-a))) * h3[i]);
    }
}

// ---------------- host launch ----------------
extern "C" void kernel_launch(void* const* d_in, const int* in_sizes, int n_in,
                              void* d_out, int out_size) {
    const float* x      = (const float*)d_in[0];
    const float* t_emb  = (const float*)d_in[1];
    const float* ln1_g  = (const float*)d_in[2];
    const float* ln1_b  = (const float*)d_in[3];
    const float* ln2_g  = (const float*)d_in[4];
    const float* ln2_b  = (const float*)d_in[5];
    const float* ada_w  = (const float*)d_in[6];
    const float* ada_b  = (const float*)d_in[7];

    const float *fus_wg, *fus_bg, *fus_wo, *ffn_w1, *ffn_w2, *ffn_w3;
    int ab;
    if (in_sizes[8] == 16384) {
        fus_wg = (const float*)d_in[8];  fus_bg = (const float*)d_in[9];
        fus_wo = (const float*)d_in[10];
        ffn_w1 = (const float*)d_in[11]; ffn_w2 = (const float*)d_in[12];
        ffn_w3 = (const float*)d_in[13];
        ab = 14;
    } else {
        ab = 8;
        fus_wg = (const float*)d_in[24]; fus_bg = (const float*)d_in[25];
        fus_wo = (const float*)d_in[26];
        ffn_w1 = (const float*)d_in[27]; ffn_w2 = (const float*)d_in[28];
        ffn_w3 = (const float*)d_in[29];
    }

    float  *st, *ada, *qkv, *obr, *gate, *xmid, *hh;
    __half *wh, *nxh, *ao4h, *fusedh, *h1h;
    cudaGetSymbolAddress((void**)&st,     g_st);
    cudaGetSymbolAddress((void**)&ada,    g_ada);
    cudaGetSymbolAddress((void**)&wh,     g_wh);
    cudaGetSymbolAddress((void**)&nxh,    g_nxh);
    cudaGetSymbolAddress((void**)&qkv,    g_qkv);
    cudaGetSymbolAddress((void**)&ao4h,   g_ao4h);
    cudaGetSymbolAddress((void**)&obr,    g_obr);
    cudaGetSymbolAddress((void**)&gate,   g_gate);
    cudaGetSymbolAddress((void**)&fusedh, g_fusedh);
    cudaGetSymbolAddress((void**)&xmid,   g_xmid);
    cudaGetSymbolAddress((void**)&hh,     g_h);
    cudaGetSymbolAddress((void**)&h1h,    g_h1h);
    float* h1 = hh;
    float* h3 = hh + TOKF;

    cudaFuncSetAttribute(attn_tc_k, cudaFuncAttributeMaxDynamicSharedMemorySize,
                         ATT_SMEM_BYTES);
    cudaFuncSetAttribute(gemm_tc, cudaFuncAttributeMaxDynamicSharedMemorySize,
                         GEMM_SMEM);

    float* out = (float*)d_out;

    // 0. transpose all GEMM weights to fp16 [N][K]
    TP17 tp;
    for (int p = 0; p < 4; p++) {
        tp.p[p * 3 + 0] = (const float*)d_in[ab + p * 4 + 0];
        tp.p[p * 3 + 1] = (const float*)d_in[ab + p * 4 + 1];
        tp.p[p * 3 + 2] = (const float*)d_in[ab + p * 4 + 2];
        tp.p[12 + p]    = (const float*)d_in[ab + p * 4 + 3];
    }
    tp.p[16] = fus_wo;
    wtrans17_k<<<dim3(32, 32, 17), 256>>>(tp, wh);
    wtrans_k<<<dim3(128, 32), 256>>>(ffn_w1, wh + W1, Dc, Fc);   // -> [4096][1024]
    wtrans_k<<<dim3(128, 32), 256>>>(ffn_w3, wh + W3, Dc, Fc);
    wtrans_k<<<dim3(32, 128), 256>>>(ffn_w2, wh + W2, Fc, Dc);   // -> [1024][4096]

    // 1. AdaLN parameters
    silu_k<<<(Bc * Dc + 255) / 256, 256>>>(t_emb, st, Bc * Dc);
    ada_k<<<(Bc * SIXD) / 8, 256>>>(st, ada_w, ada_b, ada);

    // 2. nx = modulated LN(x), fp16
    ln_mod_k<<<TOK, 256>>>(x, ln1_g, ln1_b, ada, 0, Dc, nxh);

    // 3. all 12 QKV projections in one batched launch
    dim3 gQKV(Dc / 128, TOK / 128, 12);
    gemm_tc<<<gQKV, 256, GEMM_SMEM>>>(nxh, 0, wh + WQKV, (size_t)1 << 20,
                                      qkv, TOKD, TOK, Dc, Dc, nullptr, nullptr);

    // 4. four attention branches (fp32 in, fp16 out)
    dim3 gAttn(Sc / 128, Bc * Hc);
    dim3 gSparse(Sc / 4, Bc * Hc);
    for (int p = 0; p < 4; p++) {
        const float* q = qkv + (size_t)(3 * p + 0) * TOKD;
        const float* k = qkv + (size_t)(3 * p + 1) * TOKD;
        const float* v = qkv + (size_t)(3 * p + 2) * TOKD;
        __half* ao = ao4h + (size_t)p * TOKD;
        if (p == 1 || p == 2)
            attn_sparse_k<<<gSparse, 128>>>(q, k, v, ao, p);
        else
            attn_tc_k<<<gAttn, 256, ATT_SMEM_BYTES>>>(q, k, v, ao, p);
    }

    // 5. four Wo GEMMs batched
    dim3 gWo(Dc / 128, TOK / 128, 4);
    gemm_tc<<<gWo, 256, GEMM_SMEM>>>(ao4h, TOKD, wh + WO, (size_t)1 << 20,
                                     obr, TOKD, TOK, Dc, Dc, nullptr, nullptr);

    // 6. learned fusion + first residual (g_m at 2D)
    dim3 gProj(Dc / 128, TOK / 128, 1);
    gate_k<<<TOK, 256>>>(obr, fus_wg, fus_bg, gate);
    fusemix_k<<<(TOK * Dc) / 256, 256>>>(obr, gate, fusedh);
    gemm_tc<<<gProj, 256, GEMM_SMEM>>>(fusedh, 0, wh + WFUS, 0, xmid, 0,
                                       TOK, Dc, Dc, x, ada + 2 * Dc);

    // 7. FFN with AdaLN
    ln_mod_k<<<TOK, 256>>>(xmid, ln2_g, ln2_b, ada, 3 * Dc, 4 * Dc, nxh);
    dim3 gFfnUp(Fc / 128, TOK / 128, 2);
    gemm_tc<<<gFfnUp, 256, GEMM_SMEM>>>(nxh, 0, wh + W1, W3 - W1,
                                        h1, TOKF, TOK, Fc, Dc, nullptr, nullptr);
    size_t nf = TOKF;
    swiglu_k<<<(unsigned)((nf + 255) / 256), 256>>>(h1, h3, h1h, nf);
    gemm_tc<<<gProj, 256, GEMM_SMEM>>>(h1h, 0, wh + W2, 0, out, 0,
                                       TOK, Dc, Fc, xmid, ada + 5 * Dc);
}

// round 10
// speedup vs baseline: 1.7696x; 1.0478x over previous
#include <cuda_runtime.h>
#include <cuda_fp16.h>
#include <math.h>
#include <stdint.h>

// Problem constants
#define Bc   4
#define Sc   1024
#define Dc   1024
#define Hc   16
#define DHc  64
#define Fc   4096
#define TOK  4096          // B*S
#define SIXD 6144          // 6*D
#define TOKD ((size_t)TOK * Dc)   // 4M
#define TOKF ((size_t)TOK * Fc)   // 16M

// ---------------- scratch (no allocations allowed) ----------------
__device__ float  g_st[Bc * Dc];
__device__ float  g_ada[Bc * SIXD];
__device__ __half g_wh[(size_t)29 << 20];    // transposed fp16 weights [N][K]
__device__ __half g_nxh[TOK * Dc];           // fp16 modulated LN output
__device__ __half g_qkvh[12 * TOK * Dc];     // q,k,v fp16 (GEMM half-out)
__device__ __half g_ao4h[4 * TOK * Dc];      // attention outputs fp16
__device__ float  g_obr[4 * TOK * Dc];       // branch outputs fp32
__device__ float  g_gate[TOK * 4];
__device__ __half g_fusedh[TOK * Dc];        // fp16
__device__ float  g_xmid[TOK * Dc];
__device__ float  g_h[2 * TOK * Fc];         // h1, h3 fp32 (GEMM out)
__device__ __half g_h1h[TOK * Fc];           // fp16 swiglu output

// weight scratch offsets (elements)
#define WQKV 0
#define WO   ((size_t)12 << 20)
#define WFUS ((size_t)16 << 20)
#define W1   ((size_t)17 << 20)
#define W3   ((size_t)21 << 20)
#define W2   ((size_t)25 << 20)

// ---------------- ptx helpers ----------------
__device__ __forceinline__ void mma_f16(float* c, uint32_t a0, uint32_t a1,
                                        uint32_t a2, uint32_t a3,
                                        uint32_t b0, uint32_t b1) {
    asm("mma.sync.aligned.m16n8k16.row.col.f32.f16.f16.f32 "
        "{%0,%1,%2,%3},{%4,%5,%6,%7},{%8,%9},{%0,%1,%2,%3};"
        : "+f"(c[0]), "+f"(c[1]), "+f"(c[2]), "+f"(c[3])
        : "r"(a0), "r"(a1), "r"(a2), "r"(a3), "r"(b0), "r"(b1));
}
__device__ __forceinline__ void ldsm_x4(uint32_t& r0, uint32_t& r1,
                                        uint32_t& r2, uint32_t& r3, uint32_t addr) {
    asm volatile("ldmatrix.sync.aligned.m8n8.x4.shared.b16 {%0,%1,%2,%3}, [%4];"
                 : "=r"(r0), "=r"(r1), "=r"(r2), "=r"(r3) : "r"(addr));
}
__device__ __forceinline__ void cp16s(uint32_t smem, const void* g) {
    asm volatile("cp.async.cg.shared.global [%0], [%1], 16;" :: "r"(smem), "l"(g));
}
__device__ __forceinline__ void cp_commit() {
    asm volatile("cp.async.commit_group;");
}
template <int N>
__device__ __forceinline__ void cp_wait() {
    asm volatile("cp.async.wait_group %0;" :: "n"(N));
}

// ---------------- weight transpose to fp16 [N][K] ----------------
__global__ __launch_bounds__(256) void wtrans_k(const float* __restrict__ in,
                                                __half* __restrict__ out,
                                                int Kd, int Nd) {
    __shared__ float tile[32][33];
    int n0 = blockIdx.x * 32, k0 = blockIdx.y * 32;
    int tx = threadIdx.x & 31, ty = threadIdx.x >> 5;   // 32 x 8
    #pragma unroll
    for (int i = 0; i < 32; i += 8)
        tile[ty + i][tx] = in[(size_t)(k0 + ty + i) * Nd + n0 + tx];
    __syncthreads();
    #pragma unroll
    for (int i = 0; i < 32; i += 8)
        out[(size_t)(n0 + ty + i) * Kd + k0 + tx] = __float2half_rn(tile[tx][ty + i]);
}

struct TP17 { const float* p[17]; };
__global__ __launch_bounds__(256) void wtrans17_k(TP17 tp, __half* __restrict__ out) {
    __shared__ float tile[32][33];
    const float* in = tp.p[blockIdx.z];
    __half* o = out + ((size_t)blockIdx.z << 20);
    int n0 = blockIdx.x * 32, k0 = blockIdx.y * 32;
    int tx = threadIdx.x & 31, ty = threadIdx.x >> 5;
    #pragma unroll
    for (int i = 0; i < 32; i += 8)
        tile[ty + i][tx] = in[(size_t)(k0 + ty + i) * Dc + n0 + tx];
    __syncthreads();
    #pragma unroll
    for (int i = 0; i < 32; i += 8)
        o[(size_t)(n0 + ty + i) * Dc + k0 + tx] = __float2half_rn(tile[tx][ty + i]);
}

// ---------------- elementwise helpers ----------------
__global__ void silu_k(const float* __restrict__ in, float* __restrict__ out, int n) {
    int i = blockIdx.x * blockDim.x + threadIdx.x;
    if (i < n) { float v = in[i]; out[i] = v / (1.f + __expf(-v)); }
}

__global__ __launch_bounds__(256) void ada_k(const float* __restrict__ st,
                                             const float* __restrict__ W,
                                             const float* __restrict__ bias,
                                             float* __restrict__ out) {
    int o = blockIdx.x * 8 + (threadIdx.x >> 5);
    int lane = threadIdx.x & 31;
    int b = o / SIXD, n = o - b * SIXD;
    float acc = 0.f;
    for (int k = lane; k < Dc; k += 32)
        acc = fmaf(st[b * Dc + k], W[(size_t)k * SIXD + n], acc);
    #pragma unroll
    for (int off = 16; off; off >>= 1) acc += __shfl_xor_sync(~0u, acc, off);
    if (!lane) out[o] = acc + bias[n];
}

__global__ __launch_bounds__(256) void ln_mod_k(const float* __restrict__ X,
                                                const float* __restrict__ gam,
                                                const float* __restrict__ bet,
                                                const float* __restrict__ ada,
                                                int sh_off, int sc_off,
                                                __half* __restrict__ out) {
    int t = blockIdx.x;
    int b = t >> 10;
    int tid = threadIdx.x;
    const float* xr = X + (size_t)t * Dc;
    float s = 0.f, ss = 0.f;
    for (int i = tid; i < Dc; i += 256) { float v = xr[i]; s += v; ss = fmaf(v, v, ss); }
    __shared__ float r1[8], r2[8];
    __shared__ float muS, rsS;
    #pragma unroll
    for (int off = 16; off; off >>= 1) {
        s  += __shfl_xor_sync(~0u, s,  off);
        ss += __shfl_xor_sync(~0u, ss, off);
    }
    if ((tid & 31) == 0) { r1[tid >> 5] = s; r2[tid >> 5] = ss; }
    __syncthreads();
    if (tid < 32) {
        float a = (tid < 8) ? r1[tid] : 0.f;
        float c = (tid < 8) ? r2[tid] : 0.f;
        #pragma unroll
        for (int off = 4; off; off >>= 1) {
            a += __shfl_xor_sync(~0u, a, off);
            c += __shfl_xor_sync(~0u, c, off);
        }
        if (tid == 0) {
            float mu = a * (1.f / Dc);
            float var = c * (1.f / Dc) - mu * mu;
            muS = mu; rsS = rsqrtf(var + 1e-6f);
        }
    }
    __syncthreads();
    float mu = muS, rs = rsS;
    const float* ar = ada + b * SIXD;
    __half* orow = out + (size_t)t * Dc;
    for (int i = tid; i < Dc; i += 256) {
        float v = (xr[i] - mu) * rs * gam[i] + bet[i];
        orow[i] = __float2half_rn(fmaf(v, 1.f + ar[sc_off + i], ar[sh_off + i]));
    }
}

// ---------------- FP16 TC GEMM: 128x128 tile, ldmatrix + m16n8k16 ----------------
// C = A[M,K] @ W[K,N], Bt = W^T [N][K] fp16, A fp16 [M][K].
// Output: fp32 to C, or fp16 to Ch when Ch != nullptr.
// resid != nullptr (fp32 path only): C = resid + gate * acc
#define RS   40                      // row stride in halves (80 B)
#define ASZh (128 * RS)              // 5120 halves per matrix per stage
#define STGh (2 * ASZh)              // 10240 halves per stage
#define NSTG 4
#define STGB (STGh * 2)              // 20480 B per stage
#define GEMM_SMEM (NSTG * STGB)      // 81920 B

__global__ __launch_bounds__(256, 2) void gemm_tc(
    const __half* __restrict__ A, size_t azs,
    const __half* __restrict__ Bt, size_t bzs,
    float* __restrict__ C, __half* __restrict__ Ch, size_t czs,
    int M, int N, int K,
    const float* __restrict__ resid, const float* __restrict__ gate) {
    extern __shared__ char smraw[];
    uint32_t smbase = (uint32_t)__cvta_generic_to_shared(smraw);

    A += azs * blockIdx.z; Bt += bzs * blockIdx.z;
    if (Ch) Ch += czs * blockIdx.z; else C += czs * blockIdx.z;

    int tid = threadIdx.x;
    int bx = blockIdx.x, by = blockIdx.y;
    int w = tid >> 5, lane = tid & 31;
    int wm = (w >> 2) * 64, wn = (w & 3) * 32;
    int g = lane >> 2, t = lane & 3;
    int lm = lane & 7, lq = lane >> 3;

    float acc[4][4][4];
    #pragma unroll
    for (int i = 0; i < 4; i++)
        #pragma unroll
        for (int j = 0; j < 4; j++)
            #pragma unroll
            for (int r = 0; r < 4; r++) acc[i][j][r] = 0.f;

    const __half* Ag = A + (size_t)(by * 128) * K;
    const __half* Bg = Bt + (size_t)(bx * 128) * K;

    uint32_t aoff[4], boff[2];
    {
        int koff = (lq >> 1) * 8;
        int rA = lm + 8 * (lq & 1);
        #pragma unroll
        for (int i = 0; i < 4; i++)
            aoff[i] = (uint32_t)(((wm + 16 * i + rA) * RS + koff) * 2);
        #pragma unroll
        for (int jp = 0; jp < 2; jp++)
            boff[jp] = (uint32_t)((ASZh + (wn + 16 * jp + 8 * (lq & 1) + lm) * RS + koff) * 2);
    }

    int r0 = tid >> 2;
    int p8 = (tid & 3) * 8;

    auto load_stage = [&](int st, int k0) {
        uint32_t As = smbase + st * STGB;
        uint32_t Bs = As + ASZh * 2;
        cp16s(As + (r0 * RS + p8) * 2,        Ag + (size_t)r0 * K + k0 + p8);
        cp16s(As + ((r0 + 64) * RS + p8) * 2, Ag + (size_t)(r0 + 64) * K + k0 + p8);
        cp16s(Bs + (r0 * RS + p8) * 2,        Bg + (size_t)r0 * K + k0 + p8);
        cp16s(Bs + ((r0 + 64) * RS + p8) * 2, Bg + (size_t)(r0 + 64) * K + k0 + p8);
    };

    load_stage(0, 0);  cp_commit();
    load_stage(1, 32); cp_commit();
    load_stage(2, 64); cp_commit();
    int cur = 0;
    int nch = K >> 5;

    for (int c = 0; c < nch; c++) {
        cp_wait<2>();
        __syncthreads();
        if (c + 3 < nch) {
            int nst = cur + 3; if (nst >= NSTG) nst -= NSTG;
            load_stage(nst, (c + 3) * 32);
        }
        cp_commit();

        uint32_t stb = smbase + cur * STGB;
        #pragma unroll
        for (int ks = 0; ks < 2; ks++) {
            uint32_t kadd = stb + ks * 32;
            uint32_t af[4][4], bf[4][2];
            #pragma unroll
            for (int i = 0; i < 4; i++)
                ldsm_x4(af[i][0], af[i][1], af[i][2], af[i][3], kadd + aoff[i]);
            #pragma unroll
            for (int jp = 0; jp < 2; jp++)
                ldsm_x4(bf[2 * jp][0], bf[2 * jp + 1][0],
                        bf[2 * jp][1], bf[2 * jp + 1][1], kadd + boff[jp]);
            #pragma unroll
            for (int i = 0; i < 4; i++)
                #pragma unroll
                for (int j = 0; j < 4; j++)
                    mma_f16(acc[i][j], af[i][0], af[i][1], af[i][2], af[i][3],
                            bf[j][0], bf[j][1]);
        }
        cur++; if (cur >= NSTG) cur -= NSTG;
    }

    #pragma unroll
    for (int i = 0; i < 4; i++) {
        #pragma unroll
        for (int j = 0; j < 4; j++) {
            int row0 = by * 128 + wm + 16 * i + g;
            int col  = bx * 128 + wn + 8 * j + 2 * t;
            size_t b0i = (size_t)row0 * N + col;
            size_t b1i = (size_t)(row0 + 8) * N + col;
            if (Ch) {
                *(__half2*)&Ch[b0i] = __floats2half2_rn(acc[i][j][0], acc[i][j][1]);
                *(__half2*)&Ch[b1i] = __floats2half2_rn(acc[i][j][2], acc[i][j][3]);
            } else if (resid == nullptr) {
                *(float2*)&C[b0i] = make_float2(acc[i][j][0], acc[i][j][1]);
                *(float2*)&C[b1i] = make_float2(acc[i][j][2], acc[i][j][3]);
            } else {
                int bb0 = row0 >> 10, bb1 = (row0 + 8) >> 10;
                float2 gr0 = *(const float2*)&gate[(size_t)bb0 * SIXD + col];
                float2 gr1 = *(const float2*)&gate[(size_t)bb1 * SIXD + col];
                float2 rv0 = *(const float2*)&resid[b0i];
                float2 rv1 = *(const float2*)&resid[b1i];
                *(float2*)&C[b0i] = make_float2(fmaf(gr0.x, acc[i][j][0], rv0.x),
                                                fmaf(gr0.y, acc[i][j][1], rv0.y));
                *(float2*)&C[b1i] = make_float2(fmaf(gr1.x, acc[i][j][2], rv1.x),
                                                fmaf(gr1.y, acc[i][j][3], rv1.y));
            }
        }
    }
}

// ---------------- fp16 tensor-core flash attention (full branches) ----------------
// Q,K,V fp16 [token][Dc] head-sliced; O fp16.
// smem words (uint32/half2): Ph[128][36] | Kh[64][36] | Vt[64][36]
#define APH 36
#define ATT_SMEM_BYTES ((128 * APH + 64 * APH + 64 * APH) * 4)   // 36864 B

__global__ __launch_bounds__(256) void attn_tc_k(const __half* __restrict__ Q,
                                                 const __half* __restrict__ Km,
                                                 const __half* __restrict__ Vm,
                                                 __half* __restrict__ O, int branch) {
    extern __shared__ uint32_t smu[];
    uint32_t* Ph = smu;                 // Q stage, then P (per-warp rows)
    uint32_t* Kh = smu + 128 * APH;
    uint32_t* Vt = Kh + 64 * APH;       // [d][key-pair]
    int tid = threadIdx.x, lane = tid & 31, w = tid >> 5;
    int g = lane >> 2, t = lane & 3;
    int bh = blockIdx.y;
    int b = bh >> 4, h = bh & 15;
    int qb = blockIdx.x * 128;
    int headoff = h * DHc;

    // stage Q: 128 rows x 8 uint4
    #pragma unroll
    for (int i = 0; i < 4; i++) {
        int idx = tid + i * 256;
        int row = idx >> 3, q4 = idx & 7;
        uint4 v = *(const uint4*)&Q[((size_t)(b * Sc + qb + row)) * Dc + headoff + q4 * 8];
        *(uint4*)&Ph[row * APH + q4 * 4] = v;
    }
    __syncthreads();

    int r0 = w * 16 + g;
    uint32_t qa[4][4];
    #pragma unroll
    for (int kk = 0; kk < 4; kk++) {
        qa[kk][0] = Ph[r0 * APH + kk * 8 + t];
        qa[kk][1] = Ph[(r0 + 8) * APH + kk * 8 + t];
        qa[kk][2] = Ph[r0 * APH + kk * 8 + t + 4];
        qa[kk][3] = Ph[(r0 + 8) * APH + kk * 8 + t + 4];
    }

    float m0 = -INFINITY, m1 = -INFINITY, l0 = 0.f, l1 = 0.f;
    float o[8][4];
    #pragma unroll
    for (int j = 0; j < 8; j++)
        #pragma unroll
        for (int r = 0; r < 4; r++) o[j][r] = 0.f;

    int qi0 = qb + r0, qi1 = qi0 + 8;

    for (int kt = 0; kt < Sc; kt += 64) {
        __syncthreads();
        // K tile: 64 rows x 8 uint4
        #pragma unroll
        for (int i = 0; i < 2; i++) {
            int idx = tid + i * 256;
            int row = idx >> 3, q4 = idx & 7;
            uint4 v = *(const uint4*)&Km[((size_t)(b * Sc + kt + row)) * Dc + headoff + q4 * 8];
            *(uint4*)&Kh[row * APH + q4 * 4] = v;
        }
        // V tile transposed: thread (dg = tid>>5, kp = tid&31)
        {
            int kp = tid & 31, dg = tid >> 5;
            const __half* v0 = &Vm[((size_t)(b * Sc + kt + 2 * kp)) * Dc + headoff + dg * 8];
            uint4 va = *(const uint4*)v0;
            uint4 vb = *(const uint4*)(v0 + Dc);
            const __half* ah = (const __half*)&va;
            const __half* bh2 = (const __half*)&vb;
            #pragma unroll
            for (int j = 0; j < 8; j++) {
                __half2 hv = __halves2half2(ah[j], bh2[j]);
                Vt[(dg * 8 + j) * APH + kp] = *(const uint32_t*)&hv;
            }
        }
        __syncthreads();

        // scores: Q(16x64) @ K^T(64x64) per warp, fp16 k16 mma
        float sc[8][4];
        #pragma unroll
        for (int jn = 0; jn < 8; jn++)
            #pragma unroll
            for (int r = 0; r < 4; r++) sc[jn][r] = 0.f;
        #pragma unroll
        for (int kk = 0; kk < 4; kk++) {
            #pragma unroll
            for (int jn = 0; jn < 8; jn++) {
                uint32_t b0 = Kh[(jn * 8 + g) * APH + kk * 8 + t];
                uint32_t b1 = Kh[(jn * 8 + g) * APH + kk * 8 + t + 4];
                mma_f16(sc[jn], qa[kk][0], qa[kk][1], qa[kk][2], qa[kk][3], b0, b1);
            }
        }

        float rm0 = m0, rm1 = m1;
        #pragma unroll
        for (int jn = 0; jn < 8; jn++) {
            int kj = kt + jn * 8 + 2 * t;
            float b00 = 0.f, b01 = 0.f, b10 = 0.f, b11 = 0.f;
            if (branch == 0) {
                b00 = -(float)abs(qi0 - kj);     b01 = -(float)abs(qi0 - kj - 1);
                b10 = -(float)abs(qi1 - kj);     b11 = -(float)abs(qi1 - kj - 1);
            }
            sc[jn][0] = fmaf(sc[jn][0], 0.125f, b00);
            sc[jn][1] = fmaf(sc[jn][1], 0.125f, b01);
            sc[jn][2] = fmaf(sc[jn][2], 0.125f, b10);
            sc[jn][3] = fmaf(sc[jn][3], 0.125f, b11);
            rm0 = fmaxf(rm0, fmaxf(sc[jn][0], sc[jn][1]));
            rm1 = fmaxf(rm1, fmaxf(sc[jn][2], sc[jn][3]));
        }
        rm0 = fmaxf(rm0, __shfl_xor_sync(~0u, rm0, 1));
        rm0 = fmaxf(rm0, __shfl_xor_sync(~0u, rm0, 2));
        rm1 = fmaxf(rm1, __shfl_xor_sync(~0u, rm1, 1));
        rm1 = fmaxf(rm1, __shfl_xor_sync(~0u, rm1, 2));
        float corr0 = __expf(m0 - rm0), corr1 = __expf(m1 - rm1);
        m0 = rm0; m1 = rm1;

        float sum0 = 0.f, sum1 = 0.f;
        #pragma unroll
        for (int jn = 0; jn < 8; jn++) {
            float p0 = __expf(sc[jn][0] - m0), p1 = __expf(sc[jn][1] - m0);
            float p2 = __expf(sc[jn][2] - m1), p3 = __expf(sc[jn][3] - m1);
            sum0 += p0 + p1; sum1 += p2 + p3;
            __half2 hp0 = __floats2half2_rn(p0, p1);
            __half2 hp1 = __floats2half2_rn(p2, p3);
            Ph[r0 * APH + jn * 4 + t] = *(const uint32_t*)&hp0;
            Ph[(r0 + 8) * APH + jn * 4 + t] = *(const uint32_t*)&hp1;
        }
        sum0 += __shfl_xor_sync(~0u, sum0, 1);
        sum0 += __shfl_xor_sync(~0u, sum0, 2);
        sum1 += __shfl_xor_sync(~0u, sum1, 1);
        sum1 += __shfl_xor_sync(~0u, sum1, 2);
        l0 = fmaf(l0, corr0, sum0);
        l1 = fmaf(l1, corr1, sum1);
        #pragma unroll
        for (int jd = 0; jd < 8; jd++) {
            o[jd][0] *= corr0; o[jd][1] *= corr0;
            o[jd][2] *= corr1; o[jd][3] *= corr1;
        }
        __syncwarp();   // P rows are warp-private

        // PV: O(16x64) += P(16x64) @ V(64x64), fp16 k16 mma; B = Vt[d][key]
        #pragma unroll
        for (int ks = 0; ks < 4; ks++) {
            uint32_t pa0 = Ph[r0 * APH + ks * 8 + t];
            uint32_t pa1 = Ph[(r0 + 8) * APH + ks * 8 + t];
            uint32_t pa2 = Ph[r0 * APH + ks * 8 + t + 4];
            uint32_t pa3 = Ph[(r0 + 8) * APH + ks * 8 + t + 4];
            #pragma unroll
            for (int jd = 0; jd < 8; jd++) {
                uint32_t vb0 = Vt[(jd * 8 + g) * APH + ks * 8 + t];
                uint32_t vb1 = Vt[(jd * 8 + g) * APH + ks * 8 + t + 4];
                mma_f16(o[jd], pa0, pa1, pa2, pa3, vb0, vb1);
            }
        }
    }

    float inv0 = 1.f / l0, inv1 = 1.f / l1;
    size_t row0g = ((size_t)(b * Sc + qb + r0)) * Dc + headoff;
    size_t row1g = row0g + (size_t)8 * Dc;
    #pragma unroll
    for (int jd = 0; jd < 8; jd++) {
        int col = jd * 8 + 2 * t;
        *(__half2*)&O[row0g + col] =
            __floats2half2_rn(o[jd][0] * inv0, o[jd][1] * inv0);
        *(__half2*)&O[row1g + col] =
            __floats2half2_rn(o[jd][2] * inv1, o[jd][3] * inv1);
    }
}

// ---------------- sparse attention for masked branches (fp16 in/out) ----------------
__global__ __launch_bounds__(128) void attn_sparse_k(const __half* __restrict__ Q,
                                                     const __half* __restrict__ Km,
                                                     const __half* __restrict__ Vm,
                                                     __half* __restrict__ O, int mode) {
    int w = threadIdx.x >> 5, lane = threadIdx.x & 31;
    int qi = blockIdx.x * 4 + w;
    int bh = blockIdx.y;
    int b = bh >> 4, h = bh & 15;
    size_t rowbase = ((size_t)(b * Sc + qi)) * Dc + (size_t)h * DHc;
    float q0 = __half2float(Q[rowbase + lane]);
    float q1 = __half2float(Q[rowbase + 32 + lane]);

    int k0i, nk;
    if (mode == 1) {
        k0i = qi - 1; nk = 3;
        if (qi == 0)      { k0i = 0; nk = 2; }
        if (qi == Sc - 1) { nk = 2; }
    } else {
        k0i = qi & ~1; nk = 2;
    }

    float s[3] = {0.f, 0.f, 0.f};
    #pragma unroll 3
    for (int kk = 0; kk < 3; kk++) {
        if (kk < nk) {
            size_t kb = ((size_t)(b * Sc + k0i + kk)) * Dc + (size_t)h * DHc;
            float acc = fmaf(q0, __half2float(Km[kb + lane]),
                             q1 * __half2float(Km[kb + 32 + lane]));
            #pragma unroll
            for (int off = 16; off; off >>= 1)
                acc += __shfl_xor_sync(~0u, acc, off);
            s[kk] = acc * 0.125f;
        }
    }
    float mx = s[0];
    for (int kk = 1; kk < nk; kk++) mx = fmaxf(mx, s[kk]);
    float p[3], l = 0.f;
    for (int kk = 0; kk < nk; kk++) { p[kk] = __expf(s[kk] - mx); l += p[kk]; }
    float inv = 1.f / l;

    float o0 = 0.f, o1 = 0.f;
    #pragma unroll 3
    for (int kk = 0; kk < 3; kk++) {
        if (kk < nk) {
            size_t vb = ((size_t)(b * Sc + k0i + kk)) * Dc + (size_t)h * DHc;
            o0 = fmaf(p[kk], __half2float(Vm[vb + lane]), o0);
            o1 = fmaf(p[kk], __half2float(Vm[vb + 32 + lane]), o1);
        }
    }
    O[rowbase + lane]      = __float2half_rn(o0 * inv);
    O[rowbase + 32 + lane] = __float2half_rn(o1 * inv);
}

// ---------------- fusion gate ----------------
__global__ __launch_bounds__(256) void gate_k(const float* __restrict__ Ob,
                                              const float* __restrict__ wg,
                                              const float* __restrict__ bg,
                                              float* __restrict__ gate) {
    int t = blockIdx.x, tid = threadIdx.x;
    float4 acc = make_float4(0.f, 0.f, 0.f, 0.f);
    for (int d = tid; d < 4 * Dc; d += 256) {
        int p = d >> 10, dd = d & 1023;
        float v = Ob[((size_t)p * TOK + t) * Dc + dd];
        float4 wv = *(const float4*)&wg[(size_t)d * 4];
        acc.x = fmaf(v, wv.x, acc.x);
        acc.y = fmaf(v, wv.y, acc.y);
        acc.z = fmaf(v, wv.z, acc.z);
        acc.w = fmaf(v, wv.w, acc.w);
    }
    #pragma unroll
    for (int off = 16; off; off >>= 1) {
        acc.x += __shfl_xor_sync(~0u, acc.x, off);
        acc.y += __shfl_xor_sync(~0u, acc.y, off);
        acc.z += __shfl_xor_sync(~0u, acc.z, off);
        acc.w += __shfl_xor_sync(~0u, acc.w, off);
    }
    __shared__ float4 red[8];
    if ((tid & 31) == 0) red[tid >> 5] = acc;
    __syncthreads();
    if (tid == 0) {
        float4 a = red[0];
        #pragma unroll
        for (int i = 1; i < 8; i++) {
            a.x += red[i].x; a.y += red[i].y; a.z += red[i].z; a.w += red[i].w;
        }
        float l0 = a.x + bg[0], l1 = a.y + bg[1], l2 = a.z + bg[2], l3 = a.w + bg[3];
        float mx = fmaxf(fmaxf(l0, l1), fmaxf(l2, l3));
        float e0 = __expf(l0 - mx), e1 = __expf(l1 - mx),
              e2 = __expf(l2 - mx), e3 = __expf(l3 - mx);
        float inv = 1.f / (e0 + e1 + e2 + e3);
        gate[t * 4 + 0] = e0 * inv; gate[t * 4 + 1] = e1 * inv;
        gate[t * 4 + 2] = e2 * inv; gate[t * 4 + 3] = e3 * inv;
    }
}

__global__ void fusemix_k(const float* __restrict__ Ob,
                          const float* __restrict__ gate,
                          __half* __restrict__ out) {
    int idx = blockIdx.x * 256 + threadIdx.x;
    int t = idx >> 10;
    float g0 = gate[t * 4 + 0], g1 = gate[t * 4 + 1];
    float g2 = gate[t * 4 + 2], g3 = gate[t * 4 + 3];
    const size_t P = TOKD;
    out[idx] = __float2half_rn(g0 * Ob[idx] + g1 * Ob[idx + P] +
                               g2 * Ob[idx + 2 * P] + g3 * Ob[idx + 3 * P]);
}

__global__ void swiglu_k(const float* __restrict__ h1,
                         const float* __restrict__ h3,
                         __half* __restrict__ out, size_t n) {
    size_t i = (size_t)blockIdx.x * 256 + threadIdx.x;
    if (i < n) {
        float a = h1[i];
        out[i] = __float2half_rn((a / (1.f + __expf(-a))) * h3[i]);
    }
}

// ---------------- host launch ----------------
extern "C" void kernel_launch(void* const* d_in, const int* in_sizes, int n_in,
                              void* d_out, int out_size) {
    const float* x      = (const float*)d_in[0];
    const float* t_emb  = (const float*)d_in[1];
    const float* ln1_g  = (const float*)d_in[2];
    const float* ln1_b  = (const float*)d_in[3];
    const float* ln2_g  = (const float*)d_in[4];
    const float* ln2_b  = (const float*)d_in[5];
    const float* ada_w  = (const float*)d_in[6];
    const float* ada_b  = (const float*)d_in[7];

    const float *fus_wg, *fus_bg, *fus_wo, *ffn_w1, *ffn_w2, *ffn_w3;
    int ab;
    if (in_sizes[8] == 16384) {
        fus_wg = (const float*)d_in[8];  fus_bg = (const float*)d_in[9];
        fus_wo = (const float*)d_in[10];
        ffn_w1 = (const float*)d_in[11]; ffn_w2 = (const float*)d_in[12];
        ffn_w3 = (const float*)d_in[13];
        ab = 14;
    } else {
        ab = 8;
        fus_wg = (const float*)d_in[24]; fus_bg = (const float*)d_in[25];
        fus_wo = (const float*)d_in[26];
        ffn_w1 = (const float*)d_in[27]; ffn_w2 = (const float*)d_in[28];
        ffn_w3 = (const float*)d_in[29];
    }

    float  *st, *ada, *obr, *gate, *xmid, *hh;
    __half *wh, *nxh, *qkvh, *ao4h, *fusedh, *h1h;
    cudaGetSymbolAddress((void**)&st,     g_st);
    cudaGetSymbolAddress((void**)&ada,    g_ada);
    cudaGetSymbolAddress((void**)&wh,     g_wh);
    cudaGetSymbolAddress((void**)&nxh,    g_nxh);
    cudaGetSymbolAddress((void**)&qkvh,   g_qkvh);
    cudaGetSymbolAddress((void**)&ao4h,   g_ao4h);
    cudaGetSymbolAddress((void**)&obr,    g_obr);
    cudaGetSymbolAddress((void**)&gate,   g_gate);
    cudaGetSymbolAddress((void**)&fusedh, g_fusedh);
    cudaGetSymbolAddress((void**)&xmid,   g_xmid);
    cudaGetSymbolAddress((void**)&hh,     g_h);
    cudaGetSymbolAddress((void**)&h1h,    g_h1h);
    float* h1 = hh;
    float* h3 = hh + TOKF;

    cudaFuncSetAttribute(attn_tc_k, cudaFuncAttributeMaxDynamicSharedMemorySize,
                         ATT_SMEM_BYTES);
    cudaFuncSetAttribute(gemm_tc, cudaFuncAttributeMaxDynamicSharedMemorySize,
                         GEMM_SMEM);

    float* out = (float*)d_out;

    // 0. transpose all GEMM weights to fp16 [N][K]
    TP17 tp;
    for (int p = 0; p < 4; p++) {
        tp.p[p * 3 + 0] = (const float*)d_in[ab + p * 4 + 0];
        tp.p[p * 3 + 1] = (const float*)d_in[ab + p * 4 + 1];
        tp.p[p * 3 + 2] = (const float*)d_in[ab + p * 4 + 2];
        tp.p[12 + p]    = (const float*)d_in[ab + p * 4 + 3];
    }
    tp.p[16] = fus_wo;
    wtrans17_k<<<dim3(32, 32, 17), 256>>>(tp, wh);
    wtrans_k<<<dim3(128, 32), 256>>>(ffn_w1, wh + W1, Dc, Fc);
    wtrans_k<<<dim3(128, 32), 256>>>(ffn_w3, wh + W3, Dc, Fc);
    wtrans_k<<<dim3(32, 128), 256>>>(ffn_w2, wh + W2, Fc, Dc);

    // 1. AdaLN parameters
    silu_k<<<(Bc * Dc + 255) / 256, 256>>>(t_emb, st, Bc * Dc);
    ada_k<<<(Bc * SIXD) / 8, 256>>>(st, ada_w, ada_b, ada);

    // 2. nx = modulated LN(x), fp16
    ln_mod_k<<<TOK, 256>>>(x, ln1_g, ln1_b, ada, 0, Dc, nxh);

    // 3. all 12 QKV projections, fp16 output
    dim3 gQKV(Dc / 128, TOK / 128, 12);
    gemm_tc<<<gQKV, 256, GEMM_SMEM>>>(nxh, 0, wh + WQKV, (size_t)1 << 20,
                                      nullptr, qkvh, TOKD, TOK, Dc, Dc,
                                      nullptr, nullptr);

    // 4. four attention branches (fp16 in/out)
    dim3 gAttn(Sc / 128, Bc * Hc);
    dim3 gSparse(Sc / 4, Bc * Hc);
    for (int p = 0; p < 4; p++) {
        const __half* q = qkvh + (size_t)(3 * p + 0) * TOKD;
        const __half* k = qkvh + (size_t)(3 * p + 1) * TOKD;
        const __half* v = qkvh + (size_t)(3 * p + 2) * TOKD;
        __half* ao = ao4h + (size_t)p * TOKD;
        if (p == 1 || p == 2)
            attn_sparse_k<<<gSparse, 128>>>(q, k, v, ao, p);
        else
            attn_tc_k<<<gAttn, 256, ATT_SMEM_BYTES>>>(q, k, v, ao, p);
    }

    // 5. four Wo GEMMs batched (fp32 out)
    dim3 gWo(Dc / 128, TOK / 128, 4);
    gemm_tc<<<gWo, 256, GEMM_SMEM>>>(ao4h, TOKD, wh + WO, (size_t)1 << 20,
                                     obr, nullptr, TOKD, TOK, Dc, Dc,
                                     nullptr, nullptr);

    // 6. learned fusion + first residual (g_m at 2D)
    dim3 gProj(Dc / 128, TOK / 128, 1);
    gate_k<<<TOK, 256>>>(obr, fus_wg, fus_bg, gate);
    fusemix_k<<<(TOK * Dc) / 256, 256>>>(obr, gate, fusedh);
    gemm_tc<<<gProj, 256, GEMM_SMEM>>>(fusedh, 0, wh + WFUS, 0, xmid, nullptr, 0,
                                       TOK, Dc, Dc, x, ada + 2 * Dc);

    // 7. FFN with AdaLN
    ln_mod_k<<<TOK, 256>>>(xmid, ln2_g, ln2_b, ada, 3 * Dc, 4 * Dc, nxh);
    dim3 gFfnUp(Fc / 128, TOK / 128, 2);
    gemm_tc<<<gFfnUp, 256, GEMM_SMEM>>>(nxh, 0, wh + W1, W3 - W1,
                                        h1, nullptr, TOKF, TOK, Fc, Dc,
                                        nullptr, nullptr);
    size_t nf = TOKF;
    swiglu_k<<<(unsigned)((nf + 255) / 256), 256>>>(h1, h3, h1h, nf);
    gemm_tc<<<gProj, 256, GEMM_SMEM>>>(h1h, 0, wh + W2, 0, out, nullptr, 0,
                                       TOK, Dc, Fc, xmid, ada + 5 * Dc);
}